// round 13
// baseline (speedup 1.0000x reference)
#include <cuda_runtime.h>
#include <cstdint>

#define NB 8192
#define NM 50
#define ND 64

// =================== kernel 1 shared memory layout ==========================
// me tiles stored with XOR block swizzle (no padding):
//   word(row, col) = row*64 + ((col>>2) ^ (row&7))*4 + (col&3)
constexpr int OFF_ME0 = 0;            // 64 x 64  sample0 me (tf32, rows 50-63 zero)
constexpr int OFF_ME1 = 4096;         // 64 x 64  sample1
constexpr int OFF_B1S = 8192;         // 64   ue_b1
constexpr int OFF_ITS = 8256;         // 2 x 64 item emb
constexpr int OFF_CS  = 8384;         // 2 x 16 item-side att bias
constexpr int OFF_W2S = 8416;         // 2 x 16 at_W2
constexpr int OFF_R   = 8448;         // 2 x 256 per-half scratch (time-phased)
constexpr int OFF_MEM = 8960;         // 2 x 64 ints member ids
constexpr int SM1_FLOATS = 9088;
constexpr int SM1_BYTES  = SM1_FLOATS * 4;   // 36352 B -> 6 CTAs/SM

__device__ float g_dkl_partial[NB];
__device__ float g_hbar[NB * ND];
__device__ float g_gatt[NB * ND];
__device__ unsigned g_count = 0;      // last-block ticket (self-resetting)
// Precomputed tf32 B-fragments (written once per launch by prep_weights).
__device__ uint2 g_w1f[2048];
__device__ uint2 g_atf[512];

__device__ __forceinline__ float4 ld4(const float* p) { return __ldg((const float4*)p); }

__device__ __forceinline__ uint32_t f2tf32(float x) {
    uint32_t r;
    asm("cvt.rna.tf32.f32 %0, %1;" : "=r"(r) : "f"(x));
    return r;
}

__device__ __forceinline__ void mma_tf32(float& c0, float& c1, float& c2, float& c3,
                                         uint32_t a0, uint32_t a1, uint32_t a2, uint32_t a3,
                                         uint32_t b0, uint32_t b1)
{
    asm volatile(
        "mma.sync.aligned.m16n8k8.row.col.f32.tf32.tf32.f32 "
        "{%0,%1,%2,%3}, {%4,%5,%6,%7}, {%8,%9}, {%0,%1,%2,%3};"
        : "+f"(c0), "+f"(c1), "+f"(c2), "+f"(c3)
        : "r"(a0), "r"(a1), "r"(a2), "r"(a3), "r"(b0), "r"(b1));
}

#define HBAR(h) asm volatile("bar.sync %0, 128;" :: "r"(1 + (h)) : "memory")

// ============================ PREP KERNEL ===================================
extern "C" __global__ void __launch_bounds__(256)
prep_weights(const float* __restrict__ ue_W1, const float* __restrict__ at_W1)
{
    int idx = blockIdx.x * 256 + threadIdx.x;
    if (idx < 2048) {
        int pair = idx >> 5, lane = idx & 31;
        int ks = pair >> 3, nt = pair & 7;
        int q = lane & 3, r4 = lane >> 2;
        uint2 u;
        u.x = f2tf32(__ldg(&ue_W1[(ks * 8 + q) * 64 + nt * 8 + r4]));
        u.y = f2tf32(__ldg(&ue_W1[(ks * 8 + 4 + q) * 64 + nt * 8 + r4]));
        g_w1f[idx] = u;
    }
    int jdx = idx - 2048;
    if (jdx >= 0 && jdx < 512) {
        int pair = jdx >> 5, lane = jdx & 31;
        int ks = pair >> 1, nt = pair & 1;
        int q = lane & 3, r4 = lane >> 2;
        uint2 u;
        u.x = f2tf32(__ldg(&at_W1[(ks * 8 + q) * 16 + nt * 8 + r4]));
        u.y = f2tf32(__ldg(&at_W1[(ks * 8 + 4 + q) * 16 + nt * 8 + r4]));
        g_atf[jdx] = u;
    }
}

// ============================ KERNEL 1 ======================================
// 2 samples per 256-thread CTA; swizzled me tiles; 6 CTAs/SM target.
extern "C" __global__ void __launch_bounds__(256, 6)
agree_k1(
    const int*   __restrict__ group_inputs,
    const int*   __restrict__ item_inputs,
    const int*   __restrict__ group_members,
    const float* __restrict__ user_emb,
    const float* __restrict__ item_emb,
    const float* __restrict__ ue_b1,
    const float* __restrict__ at_W1, const float* __restrict__ at_b1,
    const float* __restrict__ at_W2, const float* __restrict__ at_b2)
{
    extern __shared__ float sm[];
    uint32_t* smu = (uint32_t*)sm;
    const int tid  = threadIdx.x;
    const int bid  = blockIdx.x;
    const int lane = tid & 31;
    const int wrp  = tid >> 5;

    int* mem0 = (int*)(sm + OFF_MEM);
    int* mem1 = (int*)(sm + OFF_MEM + 64);

    if (tid < NM) {
        mem0[tid] = group_members[group_inputs[bid * 2] * NM + tid];
    } else if (tid >= 64 && tid < 64 + NM) {
        mem1[tid - 64] = group_members[group_inputs[bid * 2 + 1] * NM + (tid - 64)];
    }
    if (tid < 64) {
        sm[OFF_ITS + tid] = __ldg(&item_emb[item_inputs[bid * 2] * ND + tid]);
    } else if (tid < 128) {
        sm[OFF_ITS + tid] = __ldg(&item_emb[item_inputs[bid * 2 + 1] * ND + (tid - 64)]);
    } else if (tid < 192) {
        sm[OFF_B1S + tid - 128] = __ldg(&ue_b1[tid - 128]);
    }
    __syncthreads();

    // ---- gather both me tiles (tf32), XOR-swizzled, rows 50..63 zero ----
    #pragma unroll
    for (int ii = 0; ii < 8; ii++) {
        int i   = tid + ii * 256;
        int row = i >> 4;
        int blk = i & 15;                 // float4 block within row
        int hf  = row >> 6, lr = row & 63;
        int base = hf ? OFF_ME1 : OFF_ME0;
        uint4 u = make_uint4(0, 0, 0, 0);
        if (lr < NM) {
            int uid = hf ? mem1[lr] : mem0[lr];
            float4 v = ld4(&user_emb[uid * ND + blk * 4]);
            u = make_uint4(f2tf32(v.x), f2tf32(v.y), f2tf32(v.z), f2tf32(v.w));
        }
        *(uint4*)&smu[base + lr * 64 + ((blk ^ (lr & 7)) << 2)] = u;
    }
    __syncthreads();

    const int half = wrp >> 2;
    const int ht   = tid & 127;
    const int mt   = wrp & 3;
    const int r4   = lane >> 2;
    const int q    = lane & 3;
    const int sid  = bid * 2 + half;
    const int meb  = half ? OFF_ME1 : OFF_ME0;
    const int RB   = OFF_R + half * 256;

    const int row0 = mt * 16 + r4, row1 = row0 + 8;
    const bool v0r = (row0 < NM), v1r = (row1 < NM);
    // swizzled bases: row0 and row1 share (row&7)=r4, rows differ by +8*64 words
    const int base0 = meb + row0 * 64 + q;
    const int base1 = base0 + 8 * 64;

    // ---- P1: h1 = me @ W1 (tensor), relu+mask colsum epilogue --------------
    #pragma unroll
    for (int ntb = 0; ntb < 2; ntb++) {
        float c[4][4] = {};
        #pragma unroll
        for (int ks = 0; ks < 8; ks++) {
            const int e0 = ((2 * ks) ^ r4) << 2;        // blk for cols ks*8+q
            const int e2 = ((2 * ks + 1) ^ r4) << 2;    // blk for cols ks*8+4+q
            uint32_t a0 = smu[base0 + e0];
            uint32_t a1 = smu[base1 + e0];
            uint32_t a2 = smu[base0 + e2];
            uint32_t a3 = smu[base1 + e2];
            uint2 b[4];
            #pragma unroll
            for (int nt = 0; nt < 4; nt++)
                b[nt] = __ldg(&g_w1f[(ks * 8 + ntb * 4 + nt) * 32 + lane]);
            #pragma unroll
            for (int nt = 0; nt < 4; nt++)
                mma_tf32(c[nt][0], c[nt][1], c[nt][2], c[nt][3],
                         a0, a1, a2, a3, b[nt].x, b[nt].y);
        }
        #pragma unroll
        for (int nt = 0; nt < 4; nt++) {
            const int n0 = ntb * 32 + nt * 8;
            const int col0 = n0 + 2 * q, col1 = col0 + 1;
            float h00 = c[nt][0] + sm[OFF_B1S + col0], h01 = c[nt][1] + sm[OFF_B1S + col1];
            float h10 = c[nt][2] + sm[OFF_B1S + col0], h11 = c[nt][3] + sm[OFF_B1S + col1];
            float s0 = (v0r ? fmaxf(h00, 0.f) : 0.f) + (v1r ? fmaxf(h10, 0.f) : 0.f);
            float s1 = (v0r ? fmaxf(h01, 0.f) : 0.f) + (v1r ? fmaxf(h11, 0.f) : 0.f);
            #pragma unroll
            for (int o = 4; o < 32; o <<= 1) {
                s0 += __shfl_xor_sync(0xffffffff, s0, o);
                s1 += __shfl_xor_sync(0xffffffff, s1, o);
            }
            if (lane < 4) {
                sm[RB + mt * 64 + n0 + 2 * lane]     = s0;
                sm[RB + mt * 64 + n0 + 2 * lane + 1] = s1;
            }
        }
    }
    HBAR(half);

    if (ht < 64) {
        float s = sm[RB + ht] + sm[RB + 64 + ht] + sm[RB + 128 + ht] + sm[RB + 192 + ht];
        g_hbar[sid * ND + ht] = s * (1.0f / (float)NM);
    } else if (ht < 80) {
        int j = ht - 64;
        float s = __ldg(&at_b1[j]);
        #pragma unroll 8
        for (int k = 0; k < ND; k++)
            s += sm[OFF_ITS + half * 64 + k] * __ldg(&at_W1[(ND + k) * 16 + j]);
        sm[OFF_CS + half * 16 + j] = s;
    } else if (ht < 96) {
        sm[OFF_W2S + half * 16 + ht - 80] = __ldg(&at_W2[ht - 80]);
    }
    HBAR(half);

    // ---- P3+P4: attention MMA, fused relu·at_W2 epilogue -> logits ---------
    {
        float c[2][4] = {};
        #pragma unroll
        for (int ks = 0; ks < 8; ks++) {
            const int e0 = ((2 * ks) ^ r4) << 2;
            const int e2 = ((2 * ks + 1) ^ r4) << 2;
            uint32_t a0 = smu[base0 + e0];
            uint32_t a1 = smu[base1 + e0];
            uint32_t a2 = smu[base0 + e2];
            uint32_t a3 = smu[base1 + e2];
            uint2 b[2];
            #pragma unroll
            for (int nt = 0; nt < 2; nt++)
                b[nt] = __ldg(&g_atf[(ks * 2 + nt) * 32 + lane]);
            #pragma unroll
            for (int nt = 0; nt < 2; nt++)
                mma_tf32(c[nt][0], c[nt][1], c[nt][2], c[nt][3],
                         a0, a1, a2, a3, b[nt].x, b[nt].y);
        }
        float l0 = 0.f, l1 = 0.f;
        #pragma unroll
        for (int nt = 0; nt < 2; nt++) {
            const int col0 = nt * 8 + 2 * q, col1 = col0 + 1;
            float w20 = sm[OFF_W2S + half * 16 + col0];
            float w21 = sm[OFF_W2S + half * 16 + col1];
            float cc0 = sm[OFF_CS + half * 16 + col0];
            float cc1 = sm[OFF_CS + half * 16 + col1];
            l0 += fmaxf(c[nt][0] + cc0, 0.f) * w20 + fmaxf(c[nt][1] + cc1, 0.f) * w21;
            l1 += fmaxf(c[nt][2] + cc0, 0.f) * w20 + fmaxf(c[nt][3] + cc1, 0.f) * w21;
        }
        l0 += __shfl_xor_sync(0xffffffff, l0, 1);
        l0 += __shfl_xor_sync(0xffffffff, l0, 2);
        l1 += __shfl_xor_sync(0xffffffff, l1, 1);
        l1 += __shfl_xor_sync(0xffffffff, l1, 2);
        if (q == 0) {
            float b2 = __ldg(&at_b2[0]);
            sm[RB + mt * 16 + r4]     = l0 + b2;
            sm[RB + mt * 16 + r4 + 8] = l1 + b2;
        }
    }
    HBAR(half);

    if ((wrp & 3) == 0) {
        const int m0 = lane, m1 = lane + 32;
        float l0v = sm[RB + m0];
        float l1v = (m1 < NM) ? sm[RB + m1] : -3.0e38f;
        float v = fmaxf(l0v, l1v);
        #pragma unroll
        for (int o = 16; o > 0; o >>= 1) v = fmaxf(v, __shfl_xor_sync(0xffffffff, v, o));
        float e0 = __expf(l0v - v);
        float e1 = (m1 < NM) ? __expf(l1v - v) : 0.f;
        float ss = e0 + e1;
        #pragma unroll
        for (int o = 16; o > 0; o >>= 1) ss += __shfl_xor_sync(0xffffffff, ss, o);
        float inv = 1.0f / ss;
        sm[RB + 192 + m0] = e0 * inv;
        if (m1 < NM) sm[RB + 192 + m1] = e1 * inv;
    }
    HBAR(half);

    // ---- pool: g_att partials (swizzled me reads) --------------------------
    {
        const int j  = ht & 63;
        const int jb = j >> 2, jw = j & 3;
        const int mq = ht >> 6;
        const int m0 = mq * 25, m1 = m0 + 25;
        float s = 0.f;
        #pragma unroll 5
        for (int m = m0; m < m1; m++)
            s += sm[RB + 192 + m] * sm[meb + m * 64 + ((jb ^ (m & 7)) << 2) + jw];
        sm[RB + 64 + mq * 64 + j] = s;
    }
    HBAR(half);
    if (ht < 64) {
        g_gatt[sid * ND + ht] = sm[RB + 64 + ht] + sm[RB + 128 + ht];
    }
}

// ============================ KERNEL 2 (R12, unchanged) =====================
extern "C" __global__ void __launch_bounds__(128)
agree_k2(
    const int*   __restrict__ group_inputs,
    const int*   __restrict__ item_inputs,
    const float* __restrict__ item_emb,
    const float* __restrict__ group_emb,
    const float* __restrict__ ue_W2, const float* __restrict__ ue_b2,
    const float* __restrict__ ge_W1, const float* __restrict__ ge_b1,
    const float* __restrict__ ge_W2, const float* __restrict__ ge_b2,
    const float* __restrict__ pr_W1, const float* __restrict__ pr_b1,
    const float* __restrict__ pr_W2, const float* __restrict__ pr_b2,
    float* __restrict__ y_out, int out_idx)
{
    __shared__ float red[128];
    __shared__ int s_last;
    const int tid  = threadIdx.x;
    const int lane = tid & 31;
    const int wrp  = tid >> 5;
    const int sid0 = blockIdx.x * 16 + wrp * 4;
    const unsigned FULL = 0xffffffffu;

    int gidx[4], iidx[4];
    float h0[4], h1[4];
    #pragma unroll
    for (int s = 0; s < 4; s++) {
        gidx[s] = __ldg(&group_inputs[sid0 + s]);
        iidx[s] = __ldg(&item_inputs[sid0 + s]);
        h0[s] = __ldg(&g_hbar[(sid0 + s) * ND + lane]);
        h1[s] = __ldg(&g_hbar[(sid0 + s) * ND + 32 + lane]);
    }

    float u0[4], u1[4];
    {
        float b0 = __ldg(&ue_b2[2 * lane]), b1 = __ldg(&ue_b2[2 * lane + 1]);
        #pragma unroll
        for (int s = 0; s < 4; s++) { u0[s] = b0; u1[s] = b1; }
    }
    #pragma unroll
    for (int k = 0; k < 64; k++) {
        float2 w = __ldg((const float2*)&ue_W2[k * 64 + 2 * lane]);
        #pragma unroll
        for (int s = 0; s < 4; s++) {
            float a = __shfl_sync(FULL, (k < 32) ? h0[s] : h1[s], k & 31);
            u0[s] += a * w.x; u1[s] += a * w.y;
        }
    }
    #pragma unroll
    for (int s = 0; s < 4; s++) { u0[s] = fmaxf(u0[s], 0.f); u1[s] = fmaxf(u1[s], 0.f); }

    float z0[4], z1[4], z2[4];
    {
        float b0 = __ldg(&ge_b1[lane]), b1 = __ldg(&ge_b1[lane + 32]), b2 = __ldg(&ge_b1[lane + 64]);
        #pragma unroll
        for (int s = 0; s < 4; s++) { z0[s] = b0; z1[s] = b1; z2[s] = b2; }
    }
    #pragma unroll
    for (int k = 0; k < 64; k++) {
        float w0 = __ldg(&ge_W1[k * 96 + lane]);
        float w1 = __ldg(&ge_W1[k * 96 + 32 + lane]);
        float w2 = __ldg(&ge_W1[k * 96 + 64 + lane]);
        #pragma unroll
        for (int s = 0; s < 4; s++) {
            float a = __shfl_sync(FULL, (k & 1) ? u1[s] : u0[s], k >> 1);
            z0[s] += a * w0; z1[s] += a * w1; z2[s] += a * w2;
        }
    }
    #pragma unroll
    for (int s = 0; s < 4; s++) {
        z0[s] = fmaxf(z0[s], 0.f); z1[s] = fmaxf(z1[s], 0.f); z2[s] = fmaxf(z2[s], 0.f);
    }

    float m0[4], m1[4];
    {
        float b0 = __ldg(&ge_b2[2 * lane]), b1 = __ldg(&ge_b2[2 * lane + 1]);
        #pragma unroll
        for (int s = 0; s < 4; s++) { m0[s] = b0; m1[s] = b1; }
    }
    #pragma unroll
    for (int k = 0; k < 96; k++) {
        float2 w = __ldg((const float2*)&ge_W2[k * 128 + 2 * lane]);
        #pragma unroll
        for (int s = 0; s < 4; s++) {
            float a = __shfl_sync(FULL, (k < 32) ? z0[s] : ((k < 64) ? z1[s] : z2[s]), k & 31);
            m0[s] += a * w.x; m1[s] += a * w.y;
        }
    }
    float gev0[4], gev1[4];
    #pragma unroll
    for (int s = 0; s < 4; s++) {
        float2 ge = __ldg((const float2*)&group_emb[gidx[s] * ND + 2 * lane]);
        gev0[s] = ge.x; gev1[s] = ge.y;
        float d0 = ge.x - m0[s], d1 = ge.y - m1[s];
        float p = d0 * d0 + d1 * d1;
        #pragma unroll
        for (int o = 16; o > 0; o >>= 1) p += __shfl_xor_sync(FULL, p, o);
        if (lane == 0) g_dkl_partial[sid0 + s] = p;
    }

    #pragma unroll
    for (int s = 0; s < 4; s++) {
        float2 itv = __ldg((const float2*)&item_emb[iidx[s] * ND + 2 * lane]);
        float2 gav = __ldg((const float2*)&g_gatt[(sid0 + s) * ND + 2 * lane]);
        float g0 = gav.x + gev0[s], g1 = gav.y + gev1[s];
        float hj[8] = {};
        #pragma unroll
        for (int cc = 0; cc < 2; cc++) {
            int col = 2 * lane + cc;
            float gg = cc ? g1 : g0;
            float iv = cc ? itv.y : itv.x;
            float v = gg * iv;
            float4 wa0 = ld4(&pr_W1[col * 8]),         wa1 = ld4(&pr_W1[col * 8 + 4]);
            float4 wb0 = ld4(&pr_W1[(64 + col) * 8]),  wb1 = ld4(&pr_W1[(64 + col) * 8 + 4]);
            float4 wc0 = ld4(&pr_W1[(128 + col) * 8]), wc1 = ld4(&pr_W1[(128 + col) * 8 + 4]);
            hj[0] += v * wa0.x + gg * wb0.x + iv * wc0.x;
            hj[1] += v * wa0.y + gg * wb0.y + iv * wc0.y;
            hj[2] += v * wa0.z + gg * wb0.z + iv * wc0.z;
            hj[3] += v * wa0.w + gg * wb0.w + iv * wc0.w;
            hj[4] += v * wa1.x + gg * wb1.x + iv * wc1.x;
            hj[5] += v * wa1.y + gg * wb1.y + iv * wc1.y;
            hj[6] += v * wa1.z + gg * wb1.z + iv * wc1.z;
            hj[7] += v * wa1.w + gg * wb1.w + iv * wc1.w;
        }
        #pragma unroll
        for (int j = 0; j < 8; j++) {
            #pragma unroll
            for (int o = 16; o > 0; o >>= 1) hj[j] += __shfl_xor_sync(FULL, hj[j], o);
        }
        if (lane == 0) {
            float acc = __ldg(&pr_b2[0]);
            #pragma unroll
            for (int j = 0; j < 8; j++)
                acc += fmaxf(hj[j] + __ldg(&pr_b1[j]), 0.f) * __ldg(&pr_W2[j]);
            y_out[sid0 + s] = 1.0f / (1.0f + __expf(-acc));
        }
    }

    __threadfence();
    __syncthreads();
    if (tid == 0) {
        unsigned t = atomicAdd(&g_count, 1u);
        s_last = (t == gridDim.x - 1);
    }
    __syncthreads();
    if (s_last) {
        float ss = 0.f;
        #pragma unroll
        for (int i = 0; i < NB / 128; i++) ss += g_dkl_partial[tid + i * 128];
        red[tid] = ss;
        __syncthreads();
        for (int st = 64; st > 0; st >>= 1) {
            if (tid < st) red[tid] += red[tid + st];
            __syncthreads();
        }
        if (tid == 0) {
            y_out[out_idx] = red[0] * (1.0f / (float)NB);
            g_count = 0;
            __threadfence();
        }
    }
}

extern "C" void kernel_launch(void* const* d_in, const int* in_sizes, int n_in,
                              void* d_out, int out_size)
{
    cudaFuncSetAttribute(agree_k1, cudaFuncAttributeMaxDynamicSharedMemorySize, SM1_BYTES);

    prep_weights<<<10, 256>>>((const float*)d_in[6], (const float*)d_in[14]);

    agree_k1<<<NB / 2, 256, SM1_BYTES>>>(
        (const int*)d_in[0],
        (const int*)d_in[1],
        (const int*)d_in[2],
        (const float*)d_in[3],
        (const float*)d_in[4],
        (const float*)d_in[7],
        (const float*)d_in[14], (const float*)d_in[15],
        (const float*)d_in[16], (const float*)d_in[17]);

    agree_k2<<<NB / 16, 128>>>(
        (const int*)d_in[0],
        (const int*)d_in[1],
        (const float*)d_in[4],
        (const float*)d_in[5],
        (const float*)d_in[8],  (const float*)d_in[9],
        (const float*)d_in[10], (const float*)d_in[11],
        (const float*)d_in[12], (const float*)d_in[13],
        (const float*)d_in[18], (const float*)d_in[19],
        (const float*)d_in[20], (const float*)d_in[21],
        (float*)d_out, out_size - 1);
}

// round 14
// speedup vs baseline: 1.2141x; 1.2141x over previous
#include <cuda_runtime.h>
#include <cstdint>

#define NB 8192
#define NM 50
#define ND 64

// =================== kernel 1 shared memory layout (R12) ====================
constexpr int ME_ST = 68;
constexpr int OFF_ME0 = 0;            // 64 x 68  sample0 me (tf32, rows 50-63 zero)
constexpr int OFF_ME1 = 4352;         // 64 x 68  sample1
constexpr int OFF_B1S = 8704;         // 64   ue_b1
constexpr int OFF_ITS = 8768;         // 2 x 64 item emb
constexpr int OFF_CS  = 8896;         // 2 x 16 item-side att bias
constexpr int OFF_W2S = 8928;         // 2 x 16 at_W2
constexpr int OFF_R   = 8960;         // 2 x 256 per-half scratch (time-phased)
constexpr int OFF_MEM = 9472;         // 2 x 64 ints member ids
constexpr int SM1_FLOATS = 9600;
constexpr int SM1_BYTES  = SM1_FLOATS * 4;   // 38400 B -> 5 CTAs/SM

__device__ float g_dkl_partial[NB];
__device__ float g_hbar[NB * ND];
__device__ float g_gatt[NB * ND];
__device__ unsigned g_count = 0;      // last-block ticket (self-resetting)
__device__ uint2 g_w1f[2048];
__device__ uint2 g_atf[512];

__device__ __forceinline__ float4 ld4(const float* p) { return __ldg((const float4*)p); }

__device__ __forceinline__ uint32_t f2tf32(float x) {
    uint32_t r;
    asm("cvt.rna.tf32.f32 %0, %1;" : "=r"(r) : "f"(x));
    return r;
}

__device__ __forceinline__ void mma_tf32(float& c0, float& c1, float& c2, float& c3,
                                         uint32_t a0, uint32_t a1, uint32_t a2, uint32_t a3,
                                         uint32_t b0, uint32_t b1)
{
    asm volatile(
        "mma.sync.aligned.m16n8k8.row.col.f32.tf32.tf32.f32 "
        "{%0,%1,%2,%3}, {%4,%5,%6,%7}, {%8,%9}, {%0,%1,%2,%3};"
        : "+f"(c0), "+f"(c1), "+f"(c2), "+f"(c3)
        : "r"(a0), "r"(a1), "r"(a2), "r"(a3), "r"(b0), "r"(b1));
}

#define HBAR(h) asm volatile("bar.sync %0, 128;" :: "r"(1 + (h)) : "memory")

// ============================ PREP KERNEL ===================================
extern "C" __global__ void __launch_bounds__(256)
prep_weights(const float* __restrict__ ue_W1, const float* __restrict__ at_W1)
{
    int idx = blockIdx.x * 256 + threadIdx.x;
    if (idx < 2048) {
        int pair = idx >> 5, lane = idx & 31;
        int ks = pair >> 3, nt = pair & 7;
        int q = lane & 3, r4 = lane >> 2;
        uint2 u;
        u.x = f2tf32(__ldg(&ue_W1[(ks * 8 + q) * 64 + nt * 8 + r4]));
        u.y = f2tf32(__ldg(&ue_W1[(ks * 8 + 4 + q) * 64 + nt * 8 + r4]));
        g_w1f[idx] = u;
    }
    int jdx = idx - 2048;
    if (jdx >= 0 && jdx < 512) {
        int pair = jdx >> 5, lane = jdx & 31;
        int ks = pair >> 1, nt = pair & 1;
        int q = lane & 3, r4 = lane >> 2;
        uint2 u;
        u.x = f2tf32(__ldg(&at_W1[(ks * 8 + q) * 16 + nt * 8 + r4]));
        u.y = f2tf32(__ldg(&at_W1[(ks * 8 + 4 + q) * 16 + nt * 8 + r4]));
        g_atf[jdx] = u;
    }
}

// ============================ KERNEL 1 ======================================
// 2 samples per CTA; attention MMA merged into P1 pass 1 (shared A-frags).
extern "C" __global__ void __launch_bounds__(256, 5)
agree_k1(
    const int*   __restrict__ group_inputs,
    const int*   __restrict__ item_inputs,
    const int*   __restrict__ group_members,
    const float* __restrict__ user_emb,
    const float* __restrict__ item_emb,
    const float* __restrict__ ue_b1,
    const float* __restrict__ at_W1, const float* __restrict__ at_b1,
    const float* __restrict__ at_W2, const float* __restrict__ at_b2)
{
    extern __shared__ float sm[];
    uint32_t* smu = (uint32_t*)sm;
    const int tid  = threadIdx.x;
    const int bid  = blockIdx.x;
    const int lane = tid & 31;
    const int wrp  = tid >> 5;

    int* mem0 = (int*)(sm + OFF_MEM);
    int* mem1 = (int*)(sm + OFF_MEM + 64);

    if (tid < NM) {
        mem0[tid] = group_members[group_inputs[bid * 2] * NM + tid];
    } else if (tid >= 64 && tid < 64 + NM) {
        mem1[tid - 64] = group_members[group_inputs[bid * 2 + 1] * NM + (tid - 64)];
    }
    if (tid < 64) {
        sm[OFF_ITS + tid] = __ldg(&item_emb[item_inputs[bid * 2] * ND + tid]);
    } else if (tid < 128) {
        sm[OFF_ITS + tid] = __ldg(&item_emb[item_inputs[bid * 2 + 1] * ND + (tid - 64)]);
    } else if (tid < 192) {
        sm[OFF_B1S + tid - 128] = __ldg(&ue_b1[tid - 128]);
    }
    __syncthreads();

    #pragma unroll
    for (int ii = 0; ii < 8; ii++) {
        int i   = tid + ii * 256;
        int row = i >> 4;
        int c4  = (i & 15) * 4;
        int hf  = row >> 6, lr = row & 63;
        int base = hf ? OFF_ME1 : OFF_ME0;
        uint4 u = make_uint4(0, 0, 0, 0);
        if (lr < NM) {
            int uid = hf ? mem1[lr] : mem0[lr];
            float4 v = ld4(&user_emb[uid * ND + c4]);
            u = make_uint4(f2tf32(v.x), f2tf32(v.y), f2tf32(v.z), f2tf32(v.w));
        }
        *(uint4*)&smu[base + lr * ME_ST + c4] = u;
    }
    __syncthreads();

    const int half = wrp >> 2;
    const int ht   = tid & 127;
    const int mt   = wrp & 3;
    const int r4   = lane >> 2;
    const int q    = lane & 3;
    const int sid  = bid * 2 + half;
    const int meb  = half ? OFF_ME1 : OFF_ME0;
    const int RB   = OFF_R + half * 256;

    const int row0 = mt * 16 + r4, row1 = row0 + 8;
    const bool v0r = (row0 < NM), v1r = (row1 < NM);
    const int abase = meb + row0 * ME_ST + q;

    // ---- P1 pass 0 (W1 n-cols 0..31) ----
    {
        float c[4][4] = {};
        #pragma unroll
        for (int ks = 0; ks < 8; ks++) {
            uint32_t a0 = smu[abase + ks * 8];
            uint32_t a1 = smu[abase + ks * 8 + 8 * ME_ST];
            uint32_t a2 = smu[abase + ks * 8 + 4];
            uint32_t a3 = smu[abase + ks * 8 + 4 + 8 * ME_ST];
            uint2 b[4];
            #pragma unroll
            for (int nt = 0; nt < 4; nt++)
                b[nt] = __ldg(&g_w1f[(ks * 8 + nt) * 32 + lane]);
            #pragma unroll
            for (int nt = 0; nt < 4; nt++)
                mma_tf32(c[nt][0], c[nt][1], c[nt][2], c[nt][3],
                         a0, a1, a2, a3, b[nt].x, b[nt].y);
        }
        #pragma unroll
        for (int nt = 0; nt < 4; nt++) {
            const int n0 = nt * 8;
            const int col0 = n0 + 2 * q, col1 = col0 + 1;
            float h00 = c[nt][0] + sm[OFF_B1S + col0], h01 = c[nt][1] + sm[OFF_B1S + col1];
            float h10 = c[nt][2] + sm[OFF_B1S + col0], h11 = c[nt][3] + sm[OFF_B1S + col1];
            float s0 = (v0r ? fmaxf(h00, 0.f) : 0.f) + (v1r ? fmaxf(h10, 0.f) : 0.f);
            float s1 = (v0r ? fmaxf(h01, 0.f) : 0.f) + (v1r ? fmaxf(h11, 0.f) : 0.f);
            #pragma unroll
            for (int o = 4; o < 32; o <<= 1) {
                s0 += __shfl_xor_sync(0xffffffff, s0, o);
                s1 += __shfl_xor_sync(0xffffffff, s1, o);
            }
            if (lane < 4) {
                sm[RB + mt * 64 + n0 + 2 * lane]     = s0;
                sm[RB + mt * 64 + n0 + 2 * lane + 1] = s1;
            }
        }
    }

    // ---- P1 pass 1 (W1 n-cols 32..63) + attention MMA (shared A-frags) ----
    float catt[2][4] = {};
    {
        float c[4][4] = {};
        #pragma unroll
        for (int ks = 0; ks < 8; ks++) {
            uint32_t a0 = smu[abase + ks * 8];
            uint32_t a1 = smu[abase + ks * 8 + 8 * ME_ST];
            uint32_t a2 = smu[abase + ks * 8 + 4];
            uint32_t a3 = smu[abase + ks * 8 + 4 + 8 * ME_ST];
            uint2 b[4];
            #pragma unroll
            for (int nt = 0; nt < 4; nt++)
                b[nt] = __ldg(&g_w1f[(ks * 8 + 4 + nt) * 32 + lane]);
            uint2 ba[2];
            #pragma unroll
            for (int nt = 0; nt < 2; nt++)
                ba[nt] = __ldg(&g_atf[(ks * 2 + nt) * 32 + lane]);
            #pragma unroll
            for (int nt = 0; nt < 4; nt++)
                mma_tf32(c[nt][0], c[nt][1], c[nt][2], c[nt][3],
                         a0, a1, a2, a3, b[nt].x, b[nt].y);
            #pragma unroll
            for (int nt = 0; nt < 2; nt++)
                mma_tf32(catt[nt][0], catt[nt][1], catt[nt][2], catt[nt][3],
                         a0, a1, a2, a3, ba[nt].x, ba[nt].y);
        }
        #pragma unroll
        for (int nt = 0; nt < 4; nt++) {
            const int n0 = 32 + nt * 8;
            const int col0 = n0 + 2 * q, col1 = col0 + 1;
            float h00 = c[nt][0] + sm[OFF_B1S + col0], h01 = c[nt][1] + sm[OFF_B1S + col1];
            float h10 = c[nt][2] + sm[OFF_B1S + col0], h11 = c[nt][3] + sm[OFF_B1S + col1];
            float s0 = (v0r ? fmaxf(h00, 0.f) : 0.f) + (v1r ? fmaxf(h10, 0.f) : 0.f);
            float s1 = (v0r ? fmaxf(h01, 0.f) : 0.f) + (v1r ? fmaxf(h11, 0.f) : 0.f);
            #pragma unroll
            for (int o = 4; o < 32; o <<= 1) {
                s0 += __shfl_xor_sync(0xffffffff, s0, o);
                s1 += __shfl_xor_sync(0xffffffff, s1, o);
            }
            if (lane < 4) {
                sm[RB + mt * 64 + n0 + 2 * lane]     = s0;
                sm[RB + mt * 64 + n0 + 2 * lane + 1] = s1;
            }
        }
    }
    HBAR(half);

    // ---- hbar -> gmem ; c[j] ; at_W2 stage ---------------------------------
    if (ht < 64) {
        float s = sm[RB + ht] + sm[RB + 64 + ht] + sm[RB + 128 + ht] + sm[RB + 192 + ht];
        g_hbar[sid * ND + ht] = s * (1.0f / (float)NM);
    } else if (ht < 80) {
        int j = ht - 64;
        float s = __ldg(&at_b1[j]);
        #pragma unroll 8
        for (int k = 0; k < ND; k++)
            s += sm[OFF_ITS + half * 64 + k] * __ldg(&at_W1[(ND + k) * 16 + j]);
        sm[OFF_CS + half * 16 + j] = s;
    } else if (ht < 96) {
        sm[OFF_W2S + half * 16 + ht - 80] = __ldg(&at_W2[ht - 80]);
    }
    HBAR(half);

    // ---- attention epilogue from held accumulators -> logits ---------------
    {
        float l0 = 0.f, l1 = 0.f;
        #pragma unroll
        for (int nt = 0; nt < 2; nt++) {
            const int col0 = nt * 8 + 2 * q, col1 = col0 + 1;
            float w20 = sm[OFF_W2S + half * 16 + col0];
            float w21 = sm[OFF_W2S + half * 16 + col1];
            float cc0 = sm[OFF_CS + half * 16 + col0];
            float cc1 = sm[OFF_CS + half * 16 + col1];
            l0 += fmaxf(catt[nt][0] + cc0, 0.f) * w20 + fmaxf(catt[nt][1] + cc1, 0.f) * w21;
            l1 += fmaxf(catt[nt][2] + cc0, 0.f) * w20 + fmaxf(catt[nt][3] + cc1, 0.f) * w21;
        }
        l0 += __shfl_xor_sync(0xffffffff, l0, 1);
        l0 += __shfl_xor_sync(0xffffffff, l0, 2);
        l1 += __shfl_xor_sync(0xffffffff, l1, 1);
        l1 += __shfl_xor_sync(0xffffffff, l1, 2);
        if (q == 0) {
            float b2 = __ldg(&at_b2[0]);
            sm[RB + mt * 16 + r4]     = l0 + b2;
            sm[RB + mt * 16 + r4 + 8] = l1 + b2;
        }
    }
    HBAR(half);

    // ---- softmax over 50 (one warp per half) -------------------------------
    if ((wrp & 3) == 0) {
        const int m0 = lane, m1 = lane + 32;
        float l0v = sm[RB + m0];
        float l1v = (m1 < NM) ? sm[RB + m1] : -3.0e38f;
        float v = fmaxf(l0v, l1v);
        #pragma unroll
        for (int o = 16; o > 0; o >>= 1) v = fmaxf(v, __shfl_xor_sync(0xffffffff, v, o));
        float e0 = __expf(l0v - v);
        float e1 = (m1 < NM) ? __expf(l1v - v) : 0.f;
        float ss = e0 + e1;
        #pragma unroll
        for (int o = 16; o > 0; o >>= 1) ss += __shfl_xor_sync(0xffffffff, ss, o);
        float inv = 1.0f / ss;
        sm[RB + 192 + m0] = e0 * inv;
        if (m1 < NM) sm[RB + 192 + m1] = e1 * inv;
    }
    HBAR(half);

    // ---- pool: g_att partials ----------------------------------------------
    {
        const int j  = ht & 63;
        const int mq = ht >> 6;
        const int m0 = mq * 25, m1 = m0 + 25;
        float s = 0.f;
        #pragma unroll 5
        for (int m = m0; m < m1; m++)
            s += sm[RB + 192 + m] * sm[meb + m * ME_ST + j];
        sm[RB + 64 + mq * 64 + j] = s;
    }
    HBAR(half);
    if (ht < 64) {
        g_gatt[sid * ND + ht] = sm[RB + 64 + ht] + sm[RB + 128 + ht];
    }
}

// ============================ KERNEL 2 (R12, unchanged) =====================
extern "C" __global__ void __launch_bounds__(128)
agree_k2(
    const int*   __restrict__ group_inputs,
    const int*   __restrict__ item_inputs,
    const float* __restrict__ item_emb,
    const float* __restrict__ group_emb,
    const float* __restrict__ ue_W2, const float* __restrict__ ue_b2,
    const float* __restrict__ ge_W1, const float* __restrict__ ge_b1,
    const float* __restrict__ ge_W2, const float* __restrict__ ge_b2,
    const float* __restrict__ pr_W1, const float* __restrict__ pr_b1,
    const float* __restrict__ pr_W2, const float* __restrict__ pr_b2,
    float* __restrict__ y_out, int out_idx)
{
    __shared__ float red[128];
    __shared__ int s_last;
    const int tid  = threadIdx.x;
    const int lane = tid & 31;
    const int wrp  = tid >> 5;
    const int sid0 = blockIdx.x * 16 + wrp * 4;
    const unsigned FULL = 0xffffffffu;

    int gidx[4], iidx[4];
    float h0[4], h1[4];
    #pragma unroll
    for (int s = 0; s < 4; s++) {
        gidx[s] = __ldg(&group_inputs[sid0 + s]);
        iidx[s] = __ldg(&item_inputs[sid0 + s]);
        h0[s] = __ldg(&g_hbar[(sid0 + s) * ND + lane]);
        h1[s] = __ldg(&g_hbar[(sid0 + s) * ND + 32 + lane]);
    }

    float u0[4], u1[4];
    {
        float b0 = __ldg(&ue_b2[2 * lane]), b1 = __ldg(&ue_b2[2 * lane + 1]);
        #pragma unroll
        for (int s = 0; s < 4; s++) { u0[s] = b0; u1[s] = b1; }
    }
    #pragma unroll
    for (int k = 0; k < 64; k++) {
        float2 w = __ldg((const float2*)&ue_W2[k * 64 + 2 * lane]);
        #pragma unroll
        for (int s = 0; s < 4; s++) {
            float a = __shfl_sync(FULL, (k < 32) ? h0[s] : h1[s], k & 31);
            u0[s] += a * w.x; u1[s] += a * w.y;
        }
    }
    #pragma unroll
    for (int s = 0; s < 4; s++) { u0[s] = fmaxf(u0[s], 0.f); u1[s] = fmaxf(u1[s], 0.f); }

    float z0[4], z1[4], z2[4];
    {
        float b0 = __ldg(&ge_b1[lane]), b1 = __ldg(&ge_b1[lane + 32]), b2 = __ldg(&ge_b1[lane + 64]);
        #pragma unroll
        for (int s = 0; s < 4; s++) { z0[s] = b0; z1[s] = b1; z2[s] = b2; }
    }
    #pragma unroll
    for (int k = 0; k < 64; k++) {
        float w0 = __ldg(&ge_W1[k * 96 + lane]);
        float w1 = __ldg(&ge_W1[k * 96 + 32 + lane]);
        float w2 = __ldg(&ge_W1[k * 96 + 64 + lane]);
        #pragma unroll
        for (int s = 0; s < 4; s++) {
            float a = __shfl_sync(FULL, (k & 1) ? u1[s] : u0[s], k >> 1);
            z0[s] += a * w0; z1[s] += a * w1; z2[s] += a * w2;
        }
    }
    #pragma unroll
    for (int s = 0; s < 4; s++) {
        z0[s] = fmaxf(z0[s], 0.f); z1[s] = fmaxf(z1[s], 0.f); z2[s] = fmaxf(z2[s], 0.f);
    }

    float m0[4], m1[4];
    {
        float b0 = __ldg(&ge_b2[2 * lane]), b1 = __ldg(&ge_b2[2 * lane + 1]);
        #pragma unroll
        for (int s = 0; s < 4; s++) { m0[s] = b0; m1[s] = b1; }
    }
    #pragma unroll
    for (int k = 0; k < 96; k++) {
        float2 w = __ldg((const float2*)&ge_W2[k * 128 + 2 * lane]);
        #pragma unroll
        for (int s = 0; s < 4; s++) {
            float a = __shfl_sync(FULL, (k < 32) ? z0[s] : ((k < 64) ? z1[s] : z2[s]), k & 31);
            m0[s] += a * w.x; m1[s] += a * w.y;
        }
    }
    float gev0[4], gev1[4];
    #pragma unroll
    for (int s = 0; s < 4; s++) {
        float2 ge = __ldg((const float2*)&group_emb[gidx[s] * ND + 2 * lane]);
        gev0[s] = ge.x; gev1[s] = ge.y;
        float d0 = ge.x - m0[s], d1 = ge.y - m1[s];
        float p = d0 * d0 + d1 * d1;
        #pragma unroll
        for (int o = 16; o > 0; o >>= 1) p += __shfl_xor_sync(FULL, p, o);
        if (lane == 0) g_dkl_partial[sid0 + s] = p;
    }

    #pragma unroll
    for (int s = 0; s < 4; s++) {
        float2 itv = __ldg((const float2*)&item_emb[iidx[s] * ND + 2 * lane]);
        float2 gav = __ldg((const float2*)&g_gatt[(sid0 + s) * ND + 2 * lane]);
        float g0 = gav.x + gev0[s], g1 = gav.y + gev1[s];
        float hj[8] = {};
        #pragma unroll
        for (int cc = 0; cc < 2; cc++) {
            int col = 2 * lane + cc;
            float gg = cc ? g1 : g0;
            float iv = cc ? itv.y : itv.x;
            float v = gg * iv;
            float4 wa0 = ld4(&pr_W1[col * 8]),         wa1 = ld4(&pr_W1[col * 8 + 4]);
            float4 wb0 = ld4(&pr_W1[(64 + col) * 8]),  wb1 = ld4(&pr_W1[(64 + col) * 8 + 4]);
            float4 wc0 = ld4(&pr_W1[(128 + col) * 8]), wc1 = ld4(&pr_W1[(128 + col) * 8 + 4]);
            hj[0] += v * wa0.x + gg * wb0.x + iv * wc0.x;
            hj[1] += v * wa0.y + gg * wb0.y + iv * wc0.y;
            hj[2] += v * wa0.z + gg * wb0.z + iv * wc0.z;
            hj[3] += v * wa0.w + gg * wb0.w + iv * wc0.w;
            hj[4] += v * wa1.x + gg * wb1.x + iv * wc1.x;
            hj[5] += v * wa1.y + gg * wb1.y + iv * wc1.y;
            hj[6] += v * wa1.z + gg * wb1.z + iv * wc1.z;
            hj[7] += v * wa1.w + gg * wb1.w + iv * wc1.w;
        }
        #pragma unroll
        for (int j = 0; j < 8; j++) {
            #pragma unroll
            for (int o = 16; o > 0; o >>= 1) hj[j] += __shfl_xor_sync(FULL, hj[j], o);
        }
        if (lane == 0) {
            float acc = __ldg(&pr_b2[0]);
            #pragma unroll
            for (int j = 0; j < 8; j++)
                acc += fmaxf(hj[j] + __ldg(&pr_b1[j]), 0.f) * __ldg(&pr_W2[j]);
            y_out[sid0 + s] = 1.0f / (1.0f + __expf(-acc));
        }
    }

    __threadfence();
    __syncthreads();
    if (tid == 0) {
        unsigned t = atomicAdd(&g_count, 1u);
        s_last = (t == gridDim.x - 1);
    }
    __syncthreads();
    if (s_last) {
        float ss = 0.f;
        #pragma unroll
        for (int i = 0; i < NB / 128; i++) ss += g_dkl_partial[tid + i * 128];
        red[tid] = ss;
        __syncthreads();
        for (int st = 64; st > 0; st >>= 1) {
            if (tid < st) red[tid] += red[tid + st];
            __syncthreads();
        }
        if (tid == 0) {
            y_out[out_idx] = red[0] * (1.0f / (float)NB);
            g_count = 0;
            __threadfence();
        }
    }
}

extern "C" void kernel_launch(void* const* d_in, const int* in_sizes, int n_in,
                              void* d_out, int out_size)
{
    cudaFuncSetAttribute(agree_k1, cudaFuncAttributeMaxDynamicSharedMemorySize, SM1_BYTES);

    prep_weights<<<10, 256>>>((const float*)d_in[6], (const float*)d_in[14]);

    agree_k1<<<NB / 2, 256, SM1_BYTES>>>(
        (const int*)d_in[0],
        (const int*)d_in[1],
        (const int*)d_in[2],
        (const float*)d_in[3],
        (const float*)d_in[4],
        (const float*)d_in[7],
        (const float*)d_in[14], (const float*)d_in[15],
        (const float*)d_in[16], (const float*)d_in[17]);

    agree_k2<<<NB / 16, 128>>>(
        (const int*)d_in[0],
        (const int*)d_in[1],
        (const float*)d_in[4],
        (const float*)d_in[5],
        (const float*)d_in[8],  (const float*)d_in[9],
        (const float*)d_in[10], (const float*)d_in[11],
        (const float*)d_in[12], (const float*)d_in[13],
        (const float*)d_in[18], (const float*)d_in[19],
        (const float*)d_in[20], (const float*)d_in[21],
        (float*)d_out, out_size - 1);
}

// round 15
// speedup vs baseline: 1.2801x; 1.0543x over previous
#include <cuda_runtime.h>
#include <cstdint>

#define NB 8192
#define NM 50
#define ND 64

// =================== kernel 1 shared memory layout (R12/R14) ================
constexpr int ME_ST = 68;
constexpr int OFF_ME0 = 0;            // 64 x 68  sample0 me (raw fp32, rows 50-63 zero)
constexpr int OFF_ME1 = 4352;         // 64 x 68  sample1
constexpr int OFF_B1S = 8704;         // 64   ue_b1
constexpr int OFF_ITS = 8768;         // 2 x 64 item emb
constexpr int OFF_CS  = 8896;         // 2 x 16 item-side att bias
constexpr int OFF_W2S = 8928;         // 2 x 16 at_W2
constexpr int OFF_R   = 8960;         // 2 x 256 per-half scratch (time-phased)
constexpr int OFF_MEM = 9472;         // 2 x 64 ints member ids
constexpr int SM1_FLOATS = 9600;
constexpr int SM1_BYTES  = SM1_FLOATS * 4;   // 38400 B -> 5 CTAs/SM

__device__ float g_dkl_partial[NB];
__device__ float g_hbar[NB * ND];
__device__ float g_gatt[NB * ND];
__device__ unsigned g_count = 0;      // last-block ticket (self-resetting)
__device__ uint2 g_w1f[2048];
__device__ uint2 g_atf[512];

__device__ __forceinline__ float4 ld4(const float* p) { return __ldg((const float4*)p); }

__device__ __forceinline__ uint32_t f2tf32(float x) {
    uint32_t r;
    asm("cvt.rna.tf32.f32 %0, %1;" : "=r"(r) : "f"(x));
    return r;
}

__device__ __forceinline__ void mma_tf32(float& c0, float& c1, float& c2, float& c3,
                                         uint32_t a0, uint32_t a1, uint32_t a2, uint32_t a3,
                                         uint32_t b0, uint32_t b1)
{
    asm volatile(
        "mma.sync.aligned.m16n8k8.row.col.f32.tf32.tf32.f32 "
        "{%0,%1,%2,%3}, {%4,%5,%6,%7}, {%8,%9}, {%0,%1,%2,%3};"
        : "+f"(c0), "+f"(c1), "+f"(c2), "+f"(c3)
        : "r"(a0), "r"(a1), "r"(a2), "r"(a3), "r"(b0), "r"(b1));
}

#define HBAR(h) asm volatile("bar.sync %0, 128;" :: "r"(1 + (h)) : "memory")

// ============================ PREP KERNEL ===================================
extern "C" __global__ void __launch_bounds__(256)
prep_weights(const float* __restrict__ ue_W1, const float* __restrict__ at_W1)
{
    int idx = blockIdx.x * 256 + threadIdx.x;
    if (idx < 2048) {
        int pair = idx >> 5, lane = idx & 31;
        int ks = pair >> 3, nt = pair & 7;
        int q = lane & 3, r4 = lane >> 2;
        uint2 u;
        u.x = f2tf32(__ldg(&ue_W1[(ks * 8 + q) * 64 + nt * 8 + r4]));
        u.y = f2tf32(__ldg(&ue_W1[(ks * 8 + 4 + q) * 64 + nt * 8 + r4]));
        g_w1f[idx] = u;
    }
    int jdx = idx - 2048;
    if (jdx >= 0 && jdx < 512) {
        int pair = jdx >> 5, lane = jdx & 31;
        int ks = pair >> 1, nt = pair & 1;
        int q = lane & 3, r4 = lane >> 2;
        uint2 u;
        u.x = f2tf32(__ldg(&at_W1[(ks * 8 + q) * 16 + nt * 8 + r4]));
        u.y = f2tf32(__ldg(&at_W1[(ks * 8 + 4 + q) * 16 + nt * 8 + r4]));
        g_atf[jdx] = u;
    }
}

// ============================ KERNEL 1 ======================================
// 2 samples per CTA; me gathered via cp.async as raw fp32 (MMA truncates to
// tf32 in HW; pool phase reads exact fp32). Attention MMA merged into P1.
extern "C" __global__ void __launch_bounds__(256, 5)
agree_k1(
    const int*   __restrict__ group_inputs,
    const int*   __restrict__ item_inputs,
    const int*   __restrict__ group_members,
    const float* __restrict__ user_emb,
    const float* __restrict__ item_emb,
    const float* __restrict__ ue_b1,
    const float* __restrict__ at_W1, const float* __restrict__ at_b1,
    const float* __restrict__ at_W2, const float* __restrict__ at_b2)
{
    extern __shared__ float sm[];
    uint32_t* smu = (uint32_t*)sm;
    const int tid  = threadIdx.x;
    const int bid  = blockIdx.x;
    const int lane = tid & 31;
    const int wrp  = tid >> 5;

    int* mem0 = (int*)(sm + OFF_MEM);
    int* mem1 = (int*)(sm + OFF_MEM + 64);

    if (tid < NM) {
        mem0[tid] = group_members[group_inputs[bid * 2] * NM + tid];
    } else if (tid >= 64 && tid < 64 + NM) {
        mem1[tid - 64] = group_members[group_inputs[bid * 2 + 1] * NM + (tid - 64)];
    }
    if (tid < 64) {
        sm[OFF_ITS + tid] = __ldg(&item_emb[item_inputs[bid * 2] * ND + tid]);
    } else if (tid < 128) {
        sm[OFF_ITS + tid] = __ldg(&item_emb[item_inputs[bid * 2 + 1] * ND + (tid - 64)]);
    } else if (tid < 192) {
        sm[OFF_B1S + tid - 128] = __ldg(&ue_b1[tid - 128]);
    }
    __syncthreads();

    // ---- gather both me tiles via cp.async (raw fp32, zero-fill pad rows) --
    #pragma unroll
    for (int ii = 0; ii < 8; ii++) {
        int i   = tid + ii * 256;
        int row = i >> 4;
        int blk = i & 15;
        int hf  = row >> 6, lr = row & 63;
        int base = hf ? OFF_ME1 : OFF_ME0;
        uint32_t sa = (uint32_t)__cvta_generic_to_shared(&smu[base + lr * ME_ST + blk * 4]);
        const float* src = user_emb;
        int sz = 0;
        if (lr < NM) {
            int uid = hf ? mem1[lr] : mem0[lr];
            src = &user_emb[uid * ND + blk * 4];
            sz = 16;
        }
        asm volatile("cp.async.ca.shared.global [%0], [%1], 16, %2;"
                     :: "r"(sa), "l"(src), "r"(sz));
    }
    asm volatile("cp.async.commit_group;" ::: "memory");
    asm volatile("cp.async.wait_group 0;" ::: "memory");
    __syncthreads();

    const int half = wrp >> 2;
    const int ht   = tid & 127;
    const int mt   = wrp & 3;
    const int r4   = lane >> 2;
    const int q    = lane & 3;
    const int sid  = bid * 2 + half;
    const int meb  = half ? OFF_ME1 : OFF_ME0;
    const int RB   = OFF_R + half * 256;

    const int row0 = mt * 16 + r4, row1 = row0 + 8;
    const bool v0r = (row0 < NM), v1r = (row1 < NM);
    const int abase = meb + row0 * ME_ST + q;

    // ---- P1 pass 0 (W1 n-cols 0..31) ----
    {
        float c[4][4] = {};
        #pragma unroll
        for (int ks = 0; ks < 8; ks++) {
            uint32_t a0 = smu[abase + ks * 8];
            uint32_t a1 = smu[abase + ks * 8 + 8 * ME_ST];
            uint32_t a2 = smu[abase + ks * 8 + 4];
            uint32_t a3 = smu[abase + ks * 8 + 4 + 8 * ME_ST];
            uint2 b[4];
            #pragma unroll
            for (int nt = 0; nt < 4; nt++)
                b[nt] = __ldg(&g_w1f[(ks * 8 + nt) * 32 + lane]);
            #pragma unroll
            for (int nt = 0; nt < 4; nt++)
                mma_tf32(c[nt][0], c[nt][1], c[nt][2], c[nt][3],
                         a0, a1, a2, a3, b[nt].x, b[nt].y);
        }
        #pragma unroll
        for (int nt = 0; nt < 4; nt++) {
            const int n0 = nt * 8;
            const int col0 = n0 + 2 * q, col1 = col0 + 1;
            float h00 = c[nt][0] + sm[OFF_B1S + col0], h01 = c[nt][1] + sm[OFF_B1S + col1];
            float h10 = c[nt][2] + sm[OFF_B1S + col0], h11 = c[nt][3] + sm[OFF_B1S + col1];
            float s0 = (v0r ? fmaxf(h00, 0.f) : 0.f) + (v1r ? fmaxf(h10, 0.f) : 0.f);
            float s1 = (v0r ? fmaxf(h01, 0.f) : 0.f) + (v1r ? fmaxf(h11, 0.f) : 0.f);
            #pragma unroll
            for (int o = 4; o < 32; o <<= 1) {
                s0 += __shfl_xor_sync(0xffffffff, s0, o);
                s1 += __shfl_xor_sync(0xffffffff, s1, o);
            }
            if (lane < 4) {
                sm[RB + mt * 64 + n0 + 2 * lane]     = s0;
                sm[RB + mt * 64 + n0 + 2 * lane + 1] = s1;
            }
        }
    }

    // ---- P1 pass 1 (W1 n-cols 32..63) + attention MMA (shared A-frags) ----
    float catt[2][4] = {};
    {
        float c[4][4] = {};
        #pragma unroll
        for (int ks = 0; ks < 8; ks++) {
            uint32_t a0 = smu[abase + ks * 8];
            uint32_t a1 = smu[abase + ks * 8 + 8 * ME_ST];
            uint32_t a2 = smu[abase + ks * 8 + 4];
            uint32_t a3 = smu[abase + ks * 8 + 4 + 8 * ME_ST];
            uint2 b[4];
            #pragma unroll
            for (int nt = 0; nt < 4; nt++)
                b[nt] = __ldg(&g_w1f[(ks * 8 + 4 + nt) * 32 + lane]);
            uint2 ba[2];
            #pragma unroll
            for (int nt = 0; nt < 2; nt++)
                ba[nt] = __ldg(&g_atf[(ks * 2 + nt) * 32 + lane]);
            #pragma unroll
            for (int nt = 0; nt < 4; nt++)
                mma_tf32(c[nt][0], c[nt][1], c[nt][2], c[nt][3],
                         a0, a1, a2, a3, b[nt].x, b[nt].y);
            #pragma unroll
            for (int nt = 0; nt < 2; nt++)
                mma_tf32(catt[nt][0], catt[nt][1], catt[nt][2], catt[nt][3],
                         a0, a1, a2, a3, ba[nt].x, ba[nt].y);
        }
        #pragma unroll
        for (int nt = 0; nt < 4; nt++) {
            const int n0 = 32 + nt * 8;
            const int col0 = n0 + 2 * q, col1 = col0 + 1;
            float h00 = c[nt][0] + sm[OFF_B1S + col0], h01 = c[nt][1] + sm[OFF_B1S + col1];
            float h10 = c[nt][2] + sm[OFF_B1S + col0], h11 = c[nt][3] + sm[OFF_B1S + col1];
            float s0 = (v0r ? fmaxf(h00, 0.f) : 0.f) + (v1r ? fmaxf(h10, 0.f) : 0.f);
            float s1 = (v0r ? fmaxf(h01, 0.f) : 0.f) + (v1r ? fmaxf(h11, 0.f) : 0.f);
            #pragma unroll
            for (int o = 4; o < 32; o <<= 1) {
                s0 += __shfl_xor_sync(0xffffffff, s0, o);
                s1 += __shfl_xor_sync(0xffffffff, s1, o);
            }
            if (lane < 4) {
                sm[RB + mt * 64 + n0 + 2 * lane]     = s0;
                sm[RB + mt * 64 + n0 + 2 * lane + 1] = s1;
            }
        }
    }
    HBAR(half);

    // ---- hbar -> gmem ; c[j] ; at_W2 stage ---------------------------------
    if (ht < 64) {
        float s = sm[RB + ht] + sm[RB + 64 + ht] + sm[RB + 128 + ht] + sm[RB + 192 + ht];
        g_hbar[sid * ND + ht] = s * (1.0f / (float)NM);
    } else if (ht < 80) {
        int j = ht - 64;
        float s = __ldg(&at_b1[j]);
        #pragma unroll 8
        for (int k = 0; k < ND; k++)
            s += sm[OFF_ITS + half * 64 + k] * __ldg(&at_W1[(ND + k) * 16 + j]);
        sm[OFF_CS + half * 16 + j] = s;
    } else if (ht < 96) {
        sm[OFF_W2S + half * 16 + ht - 80] = __ldg(&at_W2[ht - 80]);
    }
    HBAR(half);

    // ---- attention epilogue from held accumulators -> logits ---------------
    {
        float l0 = 0.f, l1 = 0.f;
        #pragma unroll
        for (int nt = 0; nt < 2; nt++) {
            const int col0 = nt * 8 + 2 * q, col1 = col0 + 1;
            float w20 = sm[OFF_W2S + half * 16 + col0];
            float w21 = sm[OFF_W2S + half * 16 + col1];
            float cc0 = sm[OFF_CS + half * 16 + col0];
            float cc1 = sm[OFF_CS + half * 16 + col1];
            l0 += fmaxf(catt[nt][0] + cc0, 0.f) * w20 + fmaxf(catt[nt][1] + cc1, 0.f) * w21;
            l1 += fmaxf(catt[nt][2] + cc0, 0.f) * w20 + fmaxf(catt[nt][3] + cc1, 0.f) * w21;
        }
        l0 += __shfl_xor_sync(0xffffffff, l0, 1);
        l0 += __shfl_xor_sync(0xffffffff, l0, 2);
        l1 += __shfl_xor_sync(0xffffffff, l1, 1);
        l1 += __shfl_xor_sync(0xffffffff, l1, 2);
        if (q == 0) {
            float b2 = __ldg(&at_b2[0]);
            sm[RB + mt * 16 + r4]     = l0 + b2;
            sm[RB + mt * 16 + r4 + 8] = l1 + b2;
        }
    }
    HBAR(half);

    // ---- softmax over 50 (one warp per half) -------------------------------
    if ((wrp & 3) == 0) {
        const int m0 = lane, m1 = lane + 32;
        float l0v = sm[RB + m0];
        float l1v = (m1 < NM) ? sm[RB + m1] : -3.0e38f;
        float v = fmaxf(l0v, l1v);
        #pragma unroll
        for (int o = 16; o > 0; o >>= 1) v = fmaxf(v, __shfl_xor_sync(0xffffffff, v, o));
        float e0 = __expf(l0v - v);
        float e1 = (m1 < NM) ? __expf(l1v - v) : 0.f;
        float ss = e0 + e1;
        #pragma unroll
        for (int o = 16; o > 0; o >>= 1) ss += __shfl_xor_sync(0xffffffff, ss, o);
        float inv = 1.0f / ss;
        sm[RB + 192 + m0] = e0 * inv;
        if (m1 < NM) sm[RB + 192 + m1] = e1 * inv;
    }
    HBAR(half);

    // ---- pool: g_att partials (me now exact fp32) --------------------------
    {
        const int j  = ht & 63;
        const int mq = ht >> 6;
        const int m0 = mq * 25, m1 = m0 + 25;
        float s = 0.f;
        #pragma unroll 5
        for (int m = m0; m < m1; m++)
            s += sm[RB + 192 + m] * sm[meb + m * ME_ST + j];
        sm[RB + 64 + mq * 64 + j] = s;
    }
    HBAR(half);
    if (ht < 64) {
        g_gatt[sid * ND + ht] = sm[RB + 64 + ht] + sm[RB + 128 + ht];
    }
}

// ============================ KERNEL 2 ======================================
// 2 samples per warp (low regs -> high occupancy), 256-thread CTAs,
// 16 samples/CTA, grid NB/16 = 512. Last CTA does the dkl reduction.
extern "C" __global__ void __launch_bounds__(256)
agree_k2(
    const int*   __restrict__ group_inputs,
    const int*   __restrict__ item_inputs,
    const float* __restrict__ item_emb,
    const float* __restrict__ group_emb,
    const float* __restrict__ ue_W2, const float* __restrict__ ue_b2,
    const float* __restrict__ ge_W1, const float* __restrict__ ge_b1,
    const float* __restrict__ ge_W2, const float* __restrict__ ge_b2,
    const float* __restrict__ pr_W1, const float* __restrict__ pr_b1,
    const float* __restrict__ pr_W2, const float* __restrict__ pr_b2,
    float* __restrict__ y_out, int out_idx)
{
    __shared__ float red[256];
    __shared__ int s_last;
    const int tid  = threadIdx.x;
    const int lane = tid & 31;
    const int wrp  = tid >> 5;
    const int sid0 = blockIdx.x * 16 + wrp * 2;
    const unsigned FULL = 0xffffffffu;

    int gidx[2], iidx[2];
    float h0[2], h1[2];
    #pragma unroll
    for (int s = 0; s < 2; s++) {
        gidx[s] = __ldg(&group_inputs[sid0 + s]);
        iidx[s] = __ldg(&item_inputs[sid0 + s]);
        h0[s] = __ldg(&g_hbar[(sid0 + s) * ND + lane]);
        h1[s] = __ldg(&g_hbar[(sid0 + s) * ND + 32 + lane]);
    }

    // ---- A: uagg = relu(hbar @ ue_W2 + b2) ----
    float u0[2], u1[2];
    {
        float b0 = __ldg(&ue_b2[2 * lane]), b1 = __ldg(&ue_b2[2 * lane + 1]);
        #pragma unroll
        for (int s = 0; s < 2; s++) { u0[s] = b0; u1[s] = b1; }
    }
    #pragma unroll
    for (int k = 0; k < 64; k++) {
        float2 w = __ldg((const float2*)&ue_W2[k * 64 + 2 * lane]);
        #pragma unroll
        for (int s = 0; s < 2; s++) {
            float a = __shfl_sync(FULL, (k < 32) ? h0[s] : h1[s], k & 31);
            u0[s] += a * w.x; u1[s] += a * w.y;
        }
    }
    #pragma unroll
    for (int s = 0; s < 2; s++) { u0[s] = fmaxf(u0[s], 0.f); u1[s] = fmaxf(u1[s], 0.f); }

    // ---- B: z = relu(uagg @ ge_W1 + b1); lane holds cols l, l+32, l+64 ----
    float z0[2], z1[2], z2[2];
    {
        float b0 = __ldg(&ge_b1[lane]), b1 = __ldg(&ge_b1[lane + 32]), b2 = __ldg(&ge_b1[lane + 64]);
        #pragma unroll
        for (int s = 0; s < 2; s++) { z0[s] = b0; z1[s] = b1; z2[s] = b2; }
    }
    #pragma unroll
    for (int k = 0; k < 64; k++) {
        float w0 = __ldg(&ge_W1[k * 96 + lane]);
        float w1 = __ldg(&ge_W1[k * 96 + 32 + lane]);
        float w2 = __ldg(&ge_W1[k * 96 + 64 + lane]);
        #pragma unroll
        for (int s = 0; s < 2; s++) {
            float a = __shfl_sync(FULL, (k & 1) ? u1[s] : u0[s], k >> 1);
            z0[s] += a * w0; z1[s] += a * w1; z2[s] += a * w2;
        }
    }
    #pragma unroll
    for (int s = 0; s < 2; s++) {
        z0[s] = fmaxf(z0[s], 0.f); z1[s] = fmaxf(z1[s], 0.f); z2[s] = fmaxf(z2[s], 0.f);
    }

    // ---- C: z_mu (first 64 cols of ge_W2) -> dkl ----
    float m0[2], m1[2];
    {
        float b0 = __ldg(&ge_b2[2 * lane]), b1 = __ldg(&ge_b2[2 * lane + 1]);
        #pragma unroll
        for (int s = 0; s < 2; s++) { m0[s] = b0; m1[s] = b1; }
    }
    #pragma unroll
    for (int k = 0; k < 96; k++) {
        float2 w = __ldg((const float2*)&ge_W2[k * 128 + 2 * lane]);
        #pragma unroll
        for (int s = 0; s < 2; s++) {
            float a = __shfl_sync(FULL, (k < 32) ? z0[s] : ((k < 64) ? z1[s] : z2[s]), k & 31);
            m0[s] += a * w.x; m1[s] += a * w.y;
        }
    }
    float gev0[2], gev1[2];
    #pragma unroll
    for (int s = 0; s < 2; s++) {
        float2 ge = __ldg((const float2*)&group_emb[gidx[s] * ND + 2 * lane]);
        gev0[s] = ge.x; gev1[s] = ge.y;
        float d0 = ge.x - m0[s], d1 = ge.y - m1[s];
        float p = d0 * d0 + d1 * d1;
        #pragma unroll
        for (int o = 16; o > 0; o >>= 1) p += __shfl_xor_sync(FULL, p, o);
        if (lane == 0) g_dkl_partial[sid0 + s] = p;
    }

    // ---- D: prediction head ----
    #pragma unroll
    for (int s = 0; s < 2; s++) {
        float2 itv = __ldg((const float2*)&item_emb[iidx[s] * ND + 2 * lane]);
        float2 gav = __ldg((const float2*)&g_gatt[(sid0 + s) * ND + 2 * lane]);
        float g0 = gav.x + gev0[s], g1 = gav.y + gev1[s];
        float hj[8] = {};
        #pragma unroll
        for (int cc = 0; cc < 2; cc++) {
            int col = 2 * lane + cc;
            float gg = cc ? g1 : g0;
            float iv = cc ? itv.y : itv.x;
            float v = gg * iv;
            float4 wa0 = ld4(&pr_W1[col * 8]),         wa1 = ld4(&pr_W1[col * 8 + 4]);
            float4 wb0 = ld4(&pr_W1[(64 + col) * 8]),  wb1 = ld4(&pr_W1[(64 + col) * 8 + 4]);
            float4 wc0 = ld4(&pr_W1[(128 + col) * 8]), wc1 = ld4(&pr_W1[(128 + col) * 8 + 4]);
            hj[0] += v * wa0.x + gg * wb0.x + iv * wc0.x;
            hj[1] += v * wa0.y + gg * wb0.y + iv * wc0.y;
            hj[2] += v * wa0.z + gg * wb0.z + iv * wc0.z;
            hj[3] += v * wa0.w + gg * wb0.w + iv * wc0.w;
            hj[4] += v * wa1.x + gg * wb1.x + iv * wc1.x;
            hj[5] += v * wa1.y + gg * wb1.y + iv * wc1.y;
            hj[6] += v * wa1.z + gg * wb1.z + iv * wc1.z;
            hj[7] += v * wa1.w + gg * wb1.w + iv * wc1.w;
        }
        #pragma unroll
        for (int j = 0; j < 8; j++) {
            #pragma unroll
            for (int o = 16; o > 0; o >>= 1) hj[j] += __shfl_xor_sync(FULL, hj[j], o);
        }
        if (lane == 0) {
            float acc = __ldg(&pr_b2[0]);
            #pragma unroll
            for (int j = 0; j < 8; j++)
                acc += fmaxf(hj[j] + __ldg(&pr_b1[j]), 0.f) * __ldg(&pr_W2[j]);
            y_out[sid0 + s] = 1.0f / (1.0f + __expf(-acc));
        }
    }

    // ---- last-block deterministic dkl reduction ----
    __threadfence();
    __syncthreads();
    if (tid == 0) {
        unsigned t = atomicAdd(&g_count, 1u);
        s_last = (t == gridDim.x - 1);
    }
    __syncthreads();
    if (s_last) {
        float ss = 0.f;
        #pragma unroll
        for (int i = 0; i < NB / 256; i++) ss += g_dkl_partial[tid + i * 256];
        red[tid] = ss;
        __syncthreads();
        for (int st = 128; st > 0; st >>= 1) {
            if (tid < st) red[tid] += red[tid + st];
            __syncthreads();
        }
        if (tid == 0) {
            y_out[out_idx] = red[0] * (1.0f / (float)NB);
            g_count = 0;
            __threadfence();
        }
    }
}

extern "C" void kernel_launch(void* const* d_in, const int* in_sizes, int n_in,
                              void* d_out, int out_size)
{
    cudaFuncSetAttribute(agree_k1, cudaFuncAttributeMaxDynamicSharedMemorySize, SM1_BYTES);

    prep_weights<<<10, 256>>>((const float*)d_in[6], (const float*)d_in[14]);

    agree_k1<<<NB / 2, 256, SM1_BYTES>>>(
        (const int*)d_in[0],
        (const int*)d_in[1],
        (const int*)d_in[2],
        (const float*)d_in[3],
        (const float*)d_in[4],
        (const float*)d_in[7],
        (const float*)d_in[14], (const float*)d_in[15],
        (const float*)d_in[16], (const float*)d_in[17]);

    agree_k2<<<NB / 16, 256>>>(
        (const int*)d_in[0],
        (const int*)d_in[1],
        (const float*)d_in[4],
        (const float*)d_in[5],
        (const float*)d_in[8],  (const float*)d_in[9],
        (const float*)d_in[10], (const float*)d_in[11],
        (const float*)d_in[12], (const float*)d_in[13],
        (const float*)d_in[18], (const float*)d_in[19],
        (const float*)d_in[20], (const float*)d_in[21],
        (float*)d_out, out_size - 1);
}

// round 16
// speedup vs baseline: 1.2965x; 1.0129x over previous
#include <cuda_runtime.h>
#include <cstdint>

#define NB 8192
#define NM 50
#define ND 64

// =================== kernel 1 shared memory layout ==========================
constexpr int ME_ST = 68;
constexpr int OFF_ME0 = 0;            // 64 x 68  sample0 me (raw fp32, rows 50-63 zero)
constexpr int OFF_ME1 = 4352;         // 64 x 68  sample1
constexpr int OFF_B1S = 8704;         // 64   ue_b1
constexpr int OFF_ITS = 8768;         // 2 x 64 item emb
constexpr int OFF_CS  = 8896;         // 2 x 16 item-side att bias
constexpr int OFF_W2S = 8928;         // 2 x 16 at_W2
constexpr int OFF_R   = 8960;         // 2 x 256 per-half scratch (time-phased)
constexpr int OFF_MEM = 9472;         // 2 x 64 ints member ids
constexpr int OFF_LG  = 9600;         // 2 x 64 logits -> wsm (in place)
constexpr int SM1_FLOATS = 9728;
constexpr int SM1_BYTES  = SM1_FLOATS * 4;   // 38912 B -> 5 CTAs/SM

__device__ float g_dkl_partial[NB];
__device__ float g_hbar[NB * ND];
__device__ float g_gatt[NB * ND];
__device__ unsigned g_count = 0;      // last-block ticket (self-resetting)
__device__ uint2 g_w1f[2048];
__device__ uint2 g_atf[512];

__device__ __forceinline__ float4 ld4(const float* p) { return __ldg((const float4*)p); }

__device__ __forceinline__ uint32_t f2tf32(float x) {
    uint32_t r;
    asm("cvt.rna.tf32.f32 %0, %1;" : "=r"(r) : "f"(x));
    return r;
}

__device__ __forceinline__ void mma_tf32(float& c0, float& c1, float& c2, float& c3,
                                         uint32_t a0, uint32_t a1, uint32_t a2, uint32_t a3,
                                         uint32_t b0, uint32_t b1)
{
    asm volatile(
        "mma.sync.aligned.m16n8k8.row.col.f32.tf32.tf32.f32 "
        "{%0,%1,%2,%3}, {%4,%5,%6,%7}, {%8,%9}, {%0,%1,%2,%3};"
        : "+f"(c0), "+f"(c1), "+f"(c2), "+f"(c3)
        : "r"(a0), "r"(a1), "r"(a2), "r"(a3), "r"(b0), "r"(b1));
}

#define HBAR(h) asm volatile("bar.sync %0, 128;" :: "r"(1 + (h)) : "memory")

// ============================ PREP KERNEL ===================================
extern "C" __global__ void __launch_bounds__(256)
prep_weights(const float* __restrict__ ue_W1, const float* __restrict__ at_W1)
{
    int idx = blockIdx.x * 256 + threadIdx.x;
    if (idx < 2048) {
        int pair = idx >> 5, lane = idx & 31;
        int ks = pair >> 3, nt = pair & 7;
        int q = lane & 3, r4 = lane >> 2;
        uint2 u;
        u.x = f2tf32(__ldg(&ue_W1[(ks * 8 + q) * 64 + nt * 8 + r4]));
        u.y = f2tf32(__ldg(&ue_W1[(ks * 8 + 4 + q) * 64 + nt * 8 + r4]));
        g_w1f[idx] = u;
    }
    int jdx = idx - 2048;
    if (jdx >= 0 && jdx < 512) {
        int pair = jdx >> 5, lane = jdx & 31;
        int ks = pair >> 1, nt = pair & 1;
        int q = lane & 3, r4 = lane >> 2;
        uint2 u;
        u.x = f2tf32(__ldg(&at_W1[(ks * 8 + q) * 16 + nt * 8 + r4]));
        u.y = f2tf32(__ldg(&at_W1[(ks * 8 + 4 + q) * 16 + nt * 8 + r4]));
        g_atf[jdx] = u;
    }
}

// ============================ KERNEL 1 ======================================
// 2 samples per CTA. Phase plan (per half):
//   P0 stage (ids/ITS/B1S/W2S) -> sync
//   P1 cp.async gather || c[j] compute -> wait+sync
//   P2 MMA pass0 + pass1(+att MMA + fused logit epilogue -> OFF_LG) -> HBAR
//   P3 softmax (warp0, in-place OFF_LG) || hbar write (warps1-2) -> HBAR
//   P4 pool partials -> HBAR -> gatt write
extern "C" __global__ void __launch_bounds__(256, 5)
agree_k1(
    const int*   __restrict__ group_inputs,
    const int*   __restrict__ item_inputs,
    const int*   __restrict__ group_members,
    const float* __restrict__ user_emb,
    const float* __restrict__ item_emb,
    const float* __restrict__ ue_b1,
    const float* __restrict__ at_W1, const float* __restrict__ at_b1,
    const float* __restrict__ at_W2, const float* __restrict__ at_b2)
{
    extern __shared__ float sm[];
    uint32_t* smu = (uint32_t*)sm;
    const int tid  = threadIdx.x;
    const int bid  = blockIdx.x;
    const int lane = tid & 31;
    const int wrp  = tid >> 5;

    int* mem0 = (int*)(sm + OFF_MEM);
    int* mem1 = (int*)(sm + OFF_MEM + 64);

    // ---- P0: stage ids, vectors, at_W2 ----
    if (tid < NM) {
        mem0[tid] = group_members[group_inputs[bid * 2] * NM + tid];
    } else if (tid >= 64 && tid < 64 + NM) {
        mem1[tid - 64] = group_members[group_inputs[bid * 2 + 1] * NM + (tid - 64)];
    }
    if (tid < 64) {
        sm[OFF_ITS + tid] = __ldg(&item_emb[item_inputs[bid * 2] * ND + tid]);
    } else if (tid < 128) {
        sm[OFF_ITS + tid] = __ldg(&item_emb[item_inputs[bid * 2 + 1] * ND + (tid - 64)]);
    } else if (tid < 192) {
        sm[OFF_B1S + tid - 128] = __ldg(&ue_b1[tid - 128]);
    } else if (tid < 224) {
        sm[OFF_W2S + tid - 192] = __ldg(&at_W2[(tid - 192) & 15]);
    }
    __syncthreads();

    // ---- P1: cp.async gather (raw fp32, zero-fill pad rows) || c[j] --------
    #pragma unroll
    for (int ii = 0; ii < 8; ii++) {
        int i   = tid + ii * 256;
        int row = i >> 4;
        int blk = i & 15;
        int hf  = row >> 6, lr = row & 63;
        int base = hf ? OFF_ME1 : OFF_ME0;
        uint32_t sa = (uint32_t)__cvta_generic_to_shared(&smu[base + lr * ME_ST + blk * 4]);
        const float* src = user_emb;
        int sz = 0;
        if (lr < NM) {
            int uid = hf ? mem1[lr] : mem0[lr];
            src = &user_emb[uid * ND + blk * 4];
            sz = 16;
        }
        asm volatile("cp.async.ca.shared.global [%0], [%1], 16, %2;"
                     :: "r"(sa), "l"(src), "r"(sz));
    }
    asm volatile("cp.async.commit_group;" ::: "memory");
    // c[j] for both halves on threads 64..95 (overlaps the async drain)
    if (tid >= 64 && tid < 96) {
        int hf = (tid - 64) >> 4;
        int j  = tid & 15;
        float s = __ldg(&at_b1[j]);
        #pragma unroll 8
        for (int k = 0; k < ND; k++)
            s += sm[OFF_ITS + hf * 64 + k] * __ldg(&at_W1[(ND + k) * 16 + j]);
        sm[OFF_CS + hf * 16 + j] = s;
    }
    asm volatile("cp.async.wait_group 0;" ::: "memory");
    __syncthreads();

    const int half = wrp >> 2;
    const int ht   = tid & 127;
    const int mt   = wrp & 3;
    const int r4   = lane >> 2;
    const int q    = lane & 3;
    const int sid  = bid * 2 + half;
    const int meb  = half ? OFF_ME1 : OFF_ME0;
    const int RB   = OFF_R + half * 256;
    const int LG   = OFF_LG + half * 64;

    const int row0 = mt * 16 + r4, row1 = row0 + 8;
    const bool v0r = (row0 < NM), v1r = (row1 < NM);
    const int abase = meb + row0 * ME_ST + q;

    // ---- P2 pass 0 (W1 n-cols 0..31) ----
    {
        float c[4][4] = {};
        #pragma unroll
        for (int ks = 0; ks < 8; ks++) {
            uint32_t a0 = smu[abase + ks * 8];
            uint32_t a1 = smu[abase + ks * 8 + 8 * ME_ST];
            uint32_t a2 = smu[abase + ks * 8 + 4];
            uint32_t a3 = smu[abase + ks * 8 + 4 + 8 * ME_ST];
            uint2 b[4];
            #pragma unroll
            for (int nt = 0; nt < 4; nt++)
                b[nt] = __ldg(&g_w1f[(ks * 8 + nt) * 32 + lane]);
            #pragma unroll
            for (int nt = 0; nt < 4; nt++)
                mma_tf32(c[nt][0], c[nt][1], c[nt][2], c[nt][3],
                         a0, a1, a2, a3, b[nt].x, b[nt].y);
        }
        #pragma unroll
        for (int nt = 0; nt < 4; nt++) {
            const int n0 = nt * 8;
            const int col0 = n0 + 2 * q, col1 = col0 + 1;
            float h00 = c[nt][0] + sm[OFF_B1S + col0], h01 = c[nt][1] + sm[OFF_B1S + col1];
            float h10 = c[nt][2] + sm[OFF_B1S + col0], h11 = c[nt][3] + sm[OFF_B1S + col1];
            float s0 = (v0r ? fmaxf(h00, 0.f) : 0.f) + (v1r ? fmaxf(h10, 0.f) : 0.f);
            float s1 = (v0r ? fmaxf(h01, 0.f) : 0.f) + (v1r ? fmaxf(h11, 0.f) : 0.f);
            #pragma unroll
            for (int o = 4; o < 32; o <<= 1) {
                s0 += __shfl_xor_sync(0xffffffff, s0, o);
                s1 += __shfl_xor_sync(0xffffffff, s1, o);
            }
            if (lane < 4) {
                sm[RB + mt * 64 + n0 + 2 * lane]     = s0;
                sm[RB + mt * 64 + n0 + 2 * lane + 1] = s1;
            }
        }
    }

    // ---- P2 pass 1 (W1 n-cols 32..63) + att MMA + fused logit epilogue ----
    {
        float catt[2][4] = {};
        float c[4][4] = {};
        #pragma unroll
        for (int ks = 0; ks < 8; ks++) {
            uint32_t a0 = smu[abase + ks * 8];
            uint32_t a1 = smu[abase + ks * 8 + 8 * ME_ST];
            uint32_t a2 = smu[abase + ks * 8 + 4];
            uint32_t a3 = smu[abase + ks * 8 + 4 + 8 * ME_ST];
            uint2 b[4];
            #pragma unroll
            for (int nt = 0; nt < 4; nt++)
                b[nt] = __ldg(&g_w1f[(ks * 8 + 4 + nt) * 32 + lane]);
            uint2 ba[2];
            #pragma unroll
            for (int nt = 0; nt < 2; nt++)
                ba[nt] = __ldg(&g_atf[(ks * 2 + nt) * 32 + lane]);
            #pragma unroll
            for (int nt = 0; nt < 4; nt++)
                mma_tf32(c[nt][0], c[nt][1], c[nt][2], c[nt][3],
                         a0, a1, a2, a3, b[nt].x, b[nt].y);
            #pragma unroll
            for (int nt = 0; nt < 2; nt++)
                mma_tf32(catt[nt][0], catt[nt][1], catt[nt][2], catt[nt][3],
                         a0, a1, a2, a3, ba[nt].x, ba[nt].y);
        }
        #pragma unroll
        for (int nt = 0; nt < 4; nt++) {
            const int n0 = 32 + nt * 8;
            const int col0 = n0 + 2 * q, col1 = col0 + 1;
            float h00 = c[nt][0] + sm[OFF_B1S + col0], h01 = c[nt][1] + sm[OFF_B1S + col1];
            float h10 = c[nt][2] + sm[OFF_B1S + col0], h11 = c[nt][3] + sm[OFF_B1S + col1];
            float s0 = (v0r ? fmaxf(h00, 0.f) : 0.f) + (v1r ? fmaxf(h10, 0.f) : 0.f);
            float s1 = (v0r ? fmaxf(h01, 0.f) : 0.f) + (v1r ? fmaxf(h11, 0.f) : 0.f);
            #pragma unroll
            for (int o = 4; o < 32; o <<= 1) {
                s0 += __shfl_xor_sync(0xffffffff, s0, o);
                s1 += __shfl_xor_sync(0xffffffff, s1, o);
            }
            if (lane < 4) {
                sm[RB + mt * 64 + n0 + 2 * lane]     = s0;
                sm[RB + mt * 64 + n0 + 2 * lane + 1] = s1;
            }
        }
        // fused attention epilogue (CS/W2S ready since P1)
        float l0 = 0.f, l1 = 0.f;
        #pragma unroll
        for (int nt = 0; nt < 2; nt++) {
            const int col0 = nt * 8 + 2 * q, col1 = col0 + 1;
            float w20 = sm[OFF_W2S + half * 16 + col0];
            float w21 = sm[OFF_W2S + half * 16 + col1];
            float cc0 = sm[OFF_CS + half * 16 + col0];
            float cc1 = sm[OFF_CS + half * 16 + col1];
            l0 += fmaxf(catt[nt][0] + cc0, 0.f) * w20 + fmaxf(catt[nt][1] + cc1, 0.f) * w21;
            l1 += fmaxf(catt[nt][2] + cc0, 0.f) * w20 + fmaxf(catt[nt][3] + cc1, 0.f) * w21;
        }
        l0 += __shfl_xor_sync(0xffffffff, l0, 1);
        l0 += __shfl_xor_sync(0xffffffff, l0, 2);
        l1 += __shfl_xor_sync(0xffffffff, l1, 1);
        l1 += __shfl_xor_sync(0xffffffff, l1, 2);
        if (q == 0) {
            float b2 = __ldg(&at_b2[0]);
            sm[LG + mt * 16 + r4]     = l0 + b2;
            sm[LG + mt * 16 + r4 + 8] = l1 + b2;
        }
    }
    HBAR(half);

    // ---- P3: softmax (warp0, in-place LG) || hbar write (warps 1-2) --------
    if ((wrp & 3) == 0) {
        const int m0 = lane, m1 = lane + 32;
        float l0v = sm[LG + m0];
        float l1v = (m1 < NM) ? sm[LG + m1] : -3.0e38f;
        float v = fmaxf(l0v, l1v);
        #pragma unroll
        for (int o = 16; o > 0; o >>= 1) v = fmaxf(v, __shfl_xor_sync(0xffffffff, v, o));
        float e0 = __expf(l0v - v);
        float e1 = (m1 < NM) ? __expf(l1v - v) : 0.f;
        float ss = e0 + e1;
        #pragma unroll
        for (int o = 16; o > 0; o >>= 1) ss += __shfl_xor_sync(0xffffffff, ss, o);
        float inv = 1.0f / ss;
        sm[LG + m0] = e0 * inv;
        if (m1 < NM) sm[LG + m1] = e1 * inv;
    } else if (ht >= 32 && ht < 96) {
        const int j = ht - 32;
        float s = sm[RB + j] + sm[RB + 64 + j] + sm[RB + 128 + j] + sm[RB + 192 + j];
        g_hbar[sid * ND + j] = s * (1.0f / (float)NM);
    }
    HBAR(half);

    // ---- P4: pool partials (wsm in LG) -------------------------------------
    {
        const int j  = ht & 63;
        const int mq = ht >> 6;
        const int m0 = mq * 25, m1 = m0 + 25;
        float s = 0.f;
        #pragma unroll 5
        for (int m = m0; m < m1; m++)
            s += sm[LG + m] * sm[meb + m * ME_ST + j];
        sm[RB + 64 + mq * 64 + j] = s;
    }
    HBAR(half);
    if (ht < 64) {
        g_gatt[sid * ND + ht] = sm[RB + 64 + ht] + sm[RB + 128 + ht];
    }
}

// ============================ KERNEL 2 (R15, unchanged) =====================
extern "C" __global__ void __launch_bounds__(256)
agree_k2(
    const int*   __restrict__ group_inputs,
    const int*   __restrict__ item_inputs,
    const float* __restrict__ item_emb,
    const float* __restrict__ group_emb,
    const float* __restrict__ ue_W2, const float* __restrict__ ue_b2,
    const float* __restrict__ ge_W1, const float* __restrict__ ge_b1,
    const float* __restrict__ ge_W2, const float* __restrict__ ge_b2,
    const float* __restrict__ pr_W1, const float* __restrict__ pr_b1,
    const float* __restrict__ pr_W2, const float* __restrict__ pr_b2,
    float* __restrict__ y_out, int out_idx)
{
    __shared__ float red[256];
    __shared__ int s_last;
    const int tid  = threadIdx.x;
    const int lane = tid & 31;
    const int wrp  = tid >> 5;
    const int sid0 = blockIdx.x * 16 + wrp * 2;
    const unsigned FULL = 0xffffffffu;

    int gidx[2], iidx[2];
    float h0[2], h1[2];
    #pragma unroll
    for (int s = 0; s < 2; s++) {
        gidx[s] = __ldg(&group_inputs[sid0 + s]);
        iidx[s] = __ldg(&item_inputs[sid0 + s]);
        h0[s] = __ldg(&g_hbar[(sid0 + s) * ND + lane]);
        h1[s] = __ldg(&g_hbar[(sid0 + s) * ND + 32 + lane]);
    }

    float u0[2], u1[2];
    {
        float b0 = __ldg(&ue_b2[2 * lane]), b1 = __ldg(&ue_b2[2 * lane + 1]);
        #pragma unroll
        for (int s = 0; s < 2; s++) { u0[s] = b0; u1[s] = b1; }
    }
    #pragma unroll
    for (int k = 0; k < 64; k++) {
        float2 w = __ldg((const float2*)&ue_W2[k * 64 + 2 * lane]);
        #pragma unroll
        for (int s = 0; s < 2; s++) {
            float a = __shfl_sync(FULL, (k < 32) ? h0[s] : h1[s], k & 31);
            u0[s] += a * w.x; u1[s] += a * w.y;
        }
    }
    #pragma unroll
    for (int s = 0; s < 2; s++) { u0[s] = fmaxf(u0[s], 0.f); u1[s] = fmaxf(u1[s], 0.f); }

    float z0[2], z1[2], z2[2];
    {
        float b0 = __ldg(&ge_b1[lane]), b1 = __ldg(&ge_b1[lane + 32]), b2 = __ldg(&ge_b1[lane + 64]);
        #pragma unroll
        for (int s = 0; s < 2; s++) { z0[s] = b0; z1[s] = b1; z2[s] = b2; }
    }
    #pragma unroll
    for (int k = 0; k < 64; k++) {
        float w0 = __ldg(&ge_W1[k * 96 + lane]);
        float w1 = __ldg(&ge_W1[k * 96 + 32 + lane]);
        float w2 = __ldg(&ge_W1[k * 96 + 64 + lane]);
        #pragma unroll
        for (int s = 0; s < 2; s++) {
            float a = __shfl_sync(FULL, (k & 1) ? u1[s] : u0[s], k >> 1);
            z0[s] += a * w0; z1[s] += a * w1; z2[s] += a * w2;
        }
    }
    #pragma unroll
    for (int s = 0; s < 2; s++) {
        z0[s] = fmaxf(z0[s], 0.f); z1[s] = fmaxf(z1[s], 0.f); z2[s] = fmaxf(z2[s], 0.f);
    }

    float m0[2], m1[2];
    {
        float b0 = __ldg(&ge_b2[2 * lane]), b1 = __ldg(&ge_b2[2 * lane + 1]);
        #pragma unroll
        for (int s = 0; s < 2; s++) { m0[s] = b0; m1[s] = b1; }
    }
    #pragma unroll
    for (int k = 0; k < 96; k++) {
        float2 w = __ldg((const float2*)&ge_W2[k * 128 + 2 * lane]);
        #pragma unroll
        for (int s = 0; s < 2; s++) {
            float a = __shfl_sync(FULL, (k < 32) ? z0[s] : ((k < 64) ? z1[s] : z2[s]), k & 31);
            m0[s] += a * w.x; m1[s] += a * w.y;
        }
    }
    float gev0[2], gev1[2];
    #pragma unroll
    for (int s = 0; s < 2; s++) {
        float2 ge = __ldg((const float2*)&group_emb[gidx[s] * ND + 2 * lane]);
        gev0[s] = ge.x; gev1[s] = ge.y;
        float d0 = ge.x - m0[s], d1 = ge.y - m1[s];
        float p = d0 * d0 + d1 * d1;
        #pragma unroll
        for (int o = 16; o > 0; o >>= 1) p += __shfl_xor_sync(FULL, p, o);
        if (lane == 0) g_dkl_partial[sid0 + s] = p;
    }

    #pragma unroll
    for (int s = 0; s < 2; s++) {
        float2 itv = __ldg((const float2*)&item_emb[iidx[s] * ND + 2 * lane]);
        float2 gav = __ldg((const float2*)&g_gatt[(sid0 + s) * ND + 2 * lane]);
        float g0 = gav.x + gev0[s], g1 = gav.y + gev1[s];
        float hj[8] = {};
        #pragma unroll
        for (int cc = 0; cc < 2; cc++) {
            int col = 2 * lane + cc;
            float gg = cc ? g1 : g0;
            float iv = cc ? itv.y : itv.x;
            float v = gg * iv;
            float4 wa0 = ld4(&pr_W1[col * 8]),         wa1 = ld4(&pr_W1[col * 8 + 4]);
            float4 wb0 = ld4(&pr_W1[(64 + col) * 8]),  wb1 = ld4(&pr_W1[(64 + col) * 8 + 4]);
            float4 wc0 = ld4(&pr_W1[(128 + col) * 8]), wc1 = ld4(&pr_W1[(128 + col) * 8 + 4]);
            hj[0] += v * wa0.x + gg * wb0.x + iv * wc0.x;
            hj[1] += v * wa0.y + gg * wb0.y + iv * wc0.y;
            hj[2] += v * wa0.z + gg * wb0.z + iv * wc0.z;
            hj[3] += v * wa0.w + gg * wb0.w + iv * wc0.w;
            hj[4] += v * wa1.x + gg * wb1.x + iv * wc1.x;
            hj[5] += v * wa1.y + gg * wb1.y + iv * wc1.y;
            hj[6] += v * wa1.z + gg * wb1.z + iv * wc1.z;
            hj[7] += v * wa1.w + gg * wb1.w + iv * wc1.w;
        }
        #pragma unroll
        for (int j = 0; j < 8; j++) {
            #pragma unroll
            for (int o = 16; o > 0; o >>= 1) hj[j] += __shfl_xor_sync(FULL, hj[j], o);
        }
        if (lane == 0) {
            float acc = __ldg(&pr_b2[0]);
            #pragma unroll
            for (int j = 0; j < 8; j++)
                acc += fmaxf(hj[j] + __ldg(&pr_b1[j]), 0.f) * __ldg(&pr_W2[j]);
            y_out[sid0 + s] = 1.0f / (1.0f + __expf(-acc));
        }
    }

    __threadfence();
    __syncthreads();
    if (tid == 0) {
        unsigned t = atomicAdd(&g_count, 1u);
        s_last = (t == gridDim.x - 1);
    }
    __syncthreads();
    if (s_last) {
        float ss = 0.f;
        #pragma unroll
        for (int i = 0; i < NB / 256; i++) ss += g_dkl_partial[tid + i * 256];
        red[tid] = ss;
        __syncthreads();
        for (int st = 128; st > 0; st >>= 1) {
            if (tid < st) red[tid] += red[tid + st];
            __syncthreads();
        }
        if (tid == 0) {
            y_out[out_idx] = red[0] * (1.0f / (float)NB);
            g_count = 0;
            __threadfence();
        }
    }
}

extern "C" void kernel_launch(void* const* d_in, const int* in_sizes, int n_in,
                              void* d_out, int out_size)
{
    cudaFuncSetAttribute(agree_k1, cudaFuncAttributeMaxDynamicSharedMemorySize, SM1_BYTES);

    prep_weights<<<10, 256>>>((const float*)d_in[6], (const float*)d_in[14]);

    agree_k1<<<NB / 2, 256, SM1_BYTES>>>(
        (const int*)d_in[0],
        (const int*)d_in[1],
        (const int*)d_in[2],
        (const float*)d_in[3],
        (const float*)d_in[4],
        (const float*)d_in[7],
        (const float*)d_in[14], (const float*)d_in[15],
        (const float*)d_in[16], (const float*)d_in[17]);

    agree_k2<<<NB / 16, 256>>>(
        (const int*)d_in[0],
        (const int*)d_in[1],
        (const float*)d_in[4],
        (const float*)d_in[5],
        (const float*)d_in[8],  (const float*)d_in[9],
        (const float*)d_in[10], (const float*)d_in[11],
        (const float*)d_in[12], (const float*)d_in[13],
        (const float*)d_in[18], (const float*)d_in[19],
        (const float*)d_in[20], (const float*)d_in[21],
        (float*)d_out, out_size - 1);
}

// round 17
// speedup vs baseline: 1.3096x; 1.0101x over previous
#include <cuda_runtime.h>
#include <cstdint>

#define NB 8192
#define NM 50
#define ND 64

// =================== kernel 1 shared memory layout ==========================
constexpr int ME_ST = 68;
constexpr int OFF_ME0 = 0;            // 64 x 68  sample0 me (raw fp32, rows 50-63 zero)
constexpr int OFF_ME1 = 4352;         // 64 x 68  sample1
constexpr int OFF_B1S = 8704;         // 64   ue_b1
constexpr int OFF_ITS = 8768;         // 2 x 64 item emb
constexpr int OFF_CS  = 8896;         // 2 x 16 item-side att bias
constexpr int OFF_W2S = 8928;         // 2 x 16 at_W2
constexpr int OFF_R   = 8960;         // 2 x 256 per-half scratch (time-phased)
constexpr int OFF_LG  = 9472;         // 2 x 64 logits -> wsm (in place)
constexpr int SM1_FLOATS = 9600;
constexpr int SM1_BYTES  = SM1_FLOATS * 4;   // 38400 B -> 5 CTAs/SM

__device__ float g_dkl_partial[NB];
__device__ float g_hbar[NB * ND];
__device__ float g_gatt[NB * ND];
__device__ unsigned g_count = 0;      // last-block ticket (self-resetting)
__device__ uint2 g_w1f[2048];
__device__ uint2 g_atf[512];
__device__ int   g_memflat[NB * 64];  // flattened member ids (lr<50 valid)

__device__ __forceinline__ float4 ld4(const float* p) { return __ldg((const float4*)p); }

__device__ __forceinline__ uint32_t f2tf32(float x) {
    uint32_t r;
    asm("cvt.rna.tf32.f32 %0, %1;" : "=r"(r) : "f"(x));
    return r;
}

__device__ __forceinline__ void mma_tf32(float& c0, float& c1, float& c2, float& c3,
                                         uint32_t a0, uint32_t a1, uint32_t a2, uint32_t a3,
                                         uint32_t b0, uint32_t b1)
{
    asm volatile(
        "mma.sync.aligned.m16n8k8.row.col.f32.tf32.tf32.f32 "
        "{%0,%1,%2,%3}, {%4,%5,%6,%7}, {%8,%9}, {%0,%1,%2,%3};"
        : "+f"(c0), "+f"(c1), "+f"(c2), "+f"(c3)
        : "r"(a0), "r"(a1), "r"(a2), "r"(a3), "r"(b0), "r"(b1));
}

#define HBAR(h) asm volatile("bar.sync %0, 128;" :: "r"(1 + (h)) : "memory")

// ============================ PREP KERNEL ===================================
// Weights -> tf32 MMA fragments; member indirection -> flat array.
extern "C" __global__ void __launch_bounds__(256)
prep_kernel(const float* __restrict__ ue_W1, const float* __restrict__ at_W1,
            const int* __restrict__ group_inputs, const int* __restrict__ group_members)
{
    int idx = blockIdx.x * 256 + threadIdx.x;
    if (idx < 2048) {
        int pair = idx >> 5, lane = idx & 31;
        int ks = pair >> 3, nt = pair & 7;
        int q = lane & 3, r4 = lane >> 2;
        uint2 u;
        u.x = f2tf32(__ldg(&ue_W1[(ks * 8 + q) * 64 + nt * 8 + r4]));
        u.y = f2tf32(__ldg(&ue_W1[(ks * 8 + 4 + q) * 64 + nt * 8 + r4]));
        g_w1f[idx] = u;
    } else if (idx < 2560) {
        int jdx = idx - 2048;
        int pair = jdx >> 5, lane = jdx & 31;
        int ks = pair >> 1, nt = pair & 1;
        int q = lane & 3, r4 = lane >> 2;
        uint2 u;
        u.x = f2tf32(__ldg(&at_W1[(ks * 8 + q) * 16 + nt * 8 + r4]));
        u.y = f2tf32(__ldg(&at_W1[(ks * 8 + 4 + q) * 16 + nt * 8 + r4]));
        g_atf[jdx] = u;
    }
    int fi = idx - 2560;
    if (fi >= 0 && fi < NB * 64) {
        int sid = fi >> 6, lr = fi & 63;
        if (lr < NM)
            g_memflat[fi] = __ldg(&group_members[__ldg(&group_inputs[sid]) * NM + lr]);
    }
}

// ============================ KERNEL 1 ======================================
// 2 samples per CTA. Gather uses flat ids -> cp.async issues at kernel start.
extern "C" __global__ void __launch_bounds__(256, 5)
agree_k1(
    const float* __restrict__ user_emb,
    const int*   __restrict__ item_inputs,
    const float* __restrict__ item_emb,
    const float* __restrict__ ue_b1,
    const float* __restrict__ at_W1, const float* __restrict__ at_b1,
    const float* __restrict__ at_W2, const float* __restrict__ at_b2)
{
    extern __shared__ float sm[];
    uint32_t* smu = (uint32_t*)sm;
    const int tid  = threadIdx.x;
    const int bid  = blockIdx.x;
    const int lane = tid & 31;
    const int wrp  = tid >> 5;

    // ---- P0: cp.async gather via flat ids (starts immediately) ------------
    #pragma unroll
    for (int ii = 0; ii < 8; ii++) {
        int i   = tid + ii * 256;
        int row = i >> 4;
        int blk = i & 15;
        int hf  = row >> 6, lr = row & 63;
        int base = hf ? OFF_ME1 : OFF_ME0;
        uint32_t sa = (uint32_t)__cvta_generic_to_shared(&smu[base + lr * ME_ST + blk * 4]);
        const float* src = user_emb;
        int sz = 0;
        if (lr < NM) {
            int uid = __ldg(&g_memflat[(bid * 2 + hf) * 64 + lr]);
            src = &user_emb[uid * ND + blk * 4];
            sz = 16;
        }
        asm volatile("cp.async.ca.shared.global [%0], [%1], 16, %2;"
                     :: "r"(sa), "l"(src), "r"(sz));
    }
    asm volatile("cp.async.commit_group;" ::: "memory");

    // ---- stage ITS / B1S / W2S (overlaps async gather) ----------------------
    if (tid < 64) {
        sm[OFF_ITS + tid] = __ldg(&item_emb[__ldg(&item_inputs[bid * 2]) * ND + tid]);
    } else if (tid < 128) {
        sm[OFF_ITS + tid] = __ldg(&item_emb[__ldg(&item_inputs[bid * 2 + 1]) * ND + (tid - 64)]);
    } else if (tid < 192) {
        sm[OFF_B1S + tid - 128] = __ldg(&ue_b1[tid - 128]);
    } else if (tid < 224) {
        sm[OFF_W2S + tid - 192] = __ldg(&at_W2[(tid - 192) & 15]);
    }
    __syncthreads();

    // ---- c[j] (needs ITS) ; then drain gather ------------------------------
    if (tid >= 64 && tid < 96) {
        int hf = (tid - 64) >> 4;
        int j  = tid & 15;
        float s = __ldg(&at_b1[j]);
        #pragma unroll 8
        for (int k = 0; k < ND; k++)
            s += sm[OFF_ITS + hf * 64 + k] * __ldg(&at_W1[(ND + k) * 16 + j]);
        sm[OFF_CS + hf * 16 + j] = s;
    }
    asm volatile("cp.async.wait_group 0;" ::: "memory");
    __syncthreads();

    const int half = wrp >> 2;
    const int ht   = tid & 127;
    const int mt   = wrp & 3;
    const int r4   = lane >> 2;
    const int q    = lane & 3;
    const int sid  = bid * 2 + half;
    const int meb  = half ? OFF_ME1 : OFF_ME0;
    const int RB   = OFF_R + half * 256;
    const int LG   = OFF_LG + half * 64;

    const int row0 = mt * 16 + r4, row1 = row0 + 8;
    const bool v0r = (row0 < NM), v1r = (row1 < NM);
    const int abase = meb + row0 * ME_ST + q;

    // ---- P2 pass 0 (W1 n-cols 0..31) ----
    {
        float c[4][4] = {};
        #pragma unroll
        for (int ks = 0; ks < 8; ks++) {
            uint32_t a0 = smu[abase + ks * 8];
            uint32_t a1 = smu[abase + ks * 8 + 8 * ME_ST];
            uint32_t a2 = smu[abase + ks * 8 + 4];
            uint32_t a3 = smu[abase + ks * 8 + 4 + 8 * ME_ST];
            uint2 b[4];
            #pragma unroll
            for (int nt = 0; nt < 4; nt++)
                b[nt] = __ldg(&g_w1f[(ks * 8 + nt) * 32 + lane]);
            #pragma unroll
            for (int nt = 0; nt < 4; nt++)
                mma_tf32(c[nt][0], c[nt][1], c[nt][2], c[nt][3],
                         a0, a1, a2, a3, b[nt].x, b[nt].y);
        }
        #pragma unroll
        for (int nt = 0; nt < 4; nt++) {
            const int n0 = nt * 8;
            const int col0 = n0 + 2 * q, col1 = col0 + 1;
            float h00 = c[nt][0] + sm[OFF_B1S + col0], h01 = c[nt][1] + sm[OFF_B1S + col1];
            float h10 = c[nt][2] + sm[OFF_B1S + col0], h11 = c[nt][3] + sm[OFF_B1S + col1];
            float s0 = (v0r ? fmaxf(h00, 0.f) : 0.f) + (v1r ? fmaxf(h10, 0.f) : 0.f);
            float s1 = (v0r ? fmaxf(h01, 0.f) : 0.f) + (v1r ? fmaxf(h11, 0.f) : 0.f);
            #pragma unroll
            for (int o = 4; o < 32; o <<= 1) {
                s0 += __shfl_xor_sync(0xffffffff, s0, o);
                s1 += __shfl_xor_sync(0xffffffff, s1, o);
            }
            if (lane < 4) {
                sm[RB + mt * 64 + n0 + 2 * lane]     = s0;
                sm[RB + mt * 64 + n0 + 2 * lane + 1] = s1;
            }
        }
    }

    // ---- P2 pass 1 (W1 n-cols 32..63) + att MMA + fused logit epilogue ----
    {
        float catt[2][4] = {};
        float c[4][4] = {};
        #pragma unroll
        for (int ks = 0; ks < 8; ks++) {
            uint32_t a0 = smu[abase + ks * 8];
            uint32_t a1 = smu[abase + ks * 8 + 8 * ME_ST];
            uint32_t a2 = smu[abase + ks * 8 + 4];
            uint32_t a3 = smu[abase + ks * 8 + 4 + 8 * ME_ST];
            uint2 b[4];
            #pragma unroll
            for (int nt = 0; nt < 4; nt++)
                b[nt] = __ldg(&g_w1f[(ks * 8 + 4 + nt) * 32 + lane]);
            uint2 ba[2];
            #pragma unroll
            for (int nt = 0; nt < 2; nt++)
                ba[nt] = __ldg(&g_atf[(ks * 2 + nt) * 32 + lane]);
            #pragma unroll
            for (int nt = 0; nt < 4; nt++)
                mma_tf32(c[nt][0], c[nt][1], c[nt][2], c[nt][3],
                         a0, a1, a2, a3, b[nt].x, b[nt].y);
            #pragma unroll
            for (int nt = 0; nt < 2; nt++)
                mma_tf32(catt[nt][0], catt[nt][1], catt[nt][2], catt[nt][3],
                         a0, a1, a2, a3, ba[nt].x, ba[nt].y);
        }
        #pragma unroll
        for (int nt = 0; nt < 4; nt++) {
            const int n0 = 32 + nt * 8;
            const int col0 = n0 + 2 * q, col1 = col0 + 1;
            float h00 = c[nt][0] + sm[OFF_B1S + col0], h01 = c[nt][1] + sm[OFF_B1S + col1];
            float h10 = c[nt][2] + sm[OFF_B1S + col0], h11 = c[nt][3] + sm[OFF_B1S + col1];
            float s0 = (v0r ? fmaxf(h00, 0.f) : 0.f) + (v1r ? fmaxf(h10, 0.f) : 0.f);
            float s1 = (v0r ? fmaxf(h01, 0.f) : 0.f) + (v1r ? fmaxf(h11, 0.f) : 0.f);
            #pragma unroll
            for (int o = 4; o < 32; o <<= 1) {
                s0 += __shfl_xor_sync(0xffffffff, s0, o);
                s1 += __shfl_xor_sync(0xffffffff, s1, o);
            }
            if (lane < 4) {
                sm[RB + mt * 64 + n0 + 2 * lane]     = s0;
                sm[RB + mt * 64 + n0 + 2 * lane + 1] = s1;
            }
        }
        float l0 = 0.f, l1 = 0.f;
        #pragma unroll
        for (int nt = 0; nt < 2; nt++) {
            const int col0 = nt * 8 + 2 * q, col1 = col0 + 1;
            float w20 = sm[OFF_W2S + half * 16 + col0];
            float w21 = sm[OFF_W2S + half * 16 + col1];
            float cc0 = sm[OFF_CS + half * 16 + col0];
            float cc1 = sm[OFF_CS + half * 16 + col1];
            l0 += fmaxf(catt[nt][0] + cc0, 0.f) * w20 + fmaxf(catt[nt][1] + cc1, 0.f) * w21;
            l1 += fmaxf(catt[nt][2] + cc0, 0.f) * w20 + fmaxf(catt[nt][3] + cc1, 0.f) * w21;
        }
        l0 += __shfl_xor_sync(0xffffffff, l0, 1);
        l0 += __shfl_xor_sync(0xffffffff, l0, 2);
        l1 += __shfl_xor_sync(0xffffffff, l1, 1);
        l1 += __shfl_xor_sync(0xffffffff, l1, 2);
        if (q == 0) {
            float b2 = __ldg(&at_b2[0]);
            sm[LG + mt * 16 + r4]     = l0 + b2;
            sm[LG + mt * 16 + r4 + 8] = l1 + b2;
        }
    }
    HBAR(half);

    // ---- P3: softmax (warp0, in-place LG) || hbar write (warps 1-2) --------
    if ((wrp & 3) == 0) {
        const int m0 = lane, m1 = lane + 32;
        float l0v = sm[LG + m0];
        float l1v = (m1 < NM) ? sm[LG + m1] : -3.0e38f;
        float v = fmaxf(l0v, l1v);
        #pragma unroll
        for (int o = 16; o > 0; o >>= 1) v = fmaxf(v, __shfl_xor_sync(0xffffffff, v, o));
        float e0 = __expf(l0v - v);
        float e1 = (m1 < NM) ? __expf(l1v - v) : 0.f;
        float ss = e0 + e1;
        #pragma unroll
        for (int o = 16; o > 0; o >>= 1) ss += __shfl_xor_sync(0xffffffff, ss, o);
        float inv = 1.0f / ss;
        sm[LG + m0] = e0 * inv;
        if (m1 < NM) sm[LG + m1] = e1 * inv;
    } else if (ht >= 32 && ht < 96) {
        const int j = ht - 32;
        float s = sm[RB + j] + sm[RB + 64 + j] + sm[RB + 128 + j] + sm[RB + 192 + j];
        g_hbar[sid * ND + j] = s * (1.0f / (float)NM);
    }
    HBAR(half);

    // ---- P4: pool partials (wsm in LG) -------------------------------------
    {
        const int j  = ht & 63;
        const int mq = ht >> 6;
        const int m0 = mq * 25, m1 = m0 + 25;
        float s = 0.f;
        #pragma unroll 5
        for (int m = m0; m < m1; m++)
            s += sm[LG + m] * sm[meb + m * ME_ST + j];
        sm[RB + 64 + mq * 64 + j] = s;
    }
    HBAR(half);
    if (ht < 64) {
        g_gatt[sid * ND + ht] = sm[RB + 64 + ht] + sm[RB + 128 + ht];
    }
}

// ============================ KERNEL 2 (R15/R16, unchanged) =================
extern "C" __global__ void __launch_bounds__(256)
agree_k2(
    const int*   __restrict__ group_inputs,
    const int*   __restrict__ item_inputs,
    const float* __restrict__ item_emb,
    const float* __restrict__ group_emb,
    const float* __restrict__ ue_W2, const float* __restrict__ ue_b2,
    const float* __restrict__ ge_W1, const float* __restrict__ ge_b1,
    const float* __restrict__ ge_W2, const float* __restrict__ ge_b2,
    const float* __restrict__ pr_W1, const float* __restrict__ pr_b1,
    const float* __restrict__ pr_W2, const float* __restrict__ pr_b2,
    float* __restrict__ y_out, int out_idx)
{
    __shared__ float red[256];
    __shared__ int s_last;
    const int tid  = threadIdx.x;
    const int lane = tid & 31;
    const int wrp  = tid >> 5;
    const int sid0 = blockIdx.x * 16 + wrp * 2;
    const unsigned FULL = 0xffffffffu;

    int gidx[2], iidx[2];
    float h0[2], h1[2];
    #pragma unroll
    for (int s = 0; s < 2; s++) {
        gidx[s] = __ldg(&group_inputs[sid0 + s]);
        iidx[s] = __ldg(&item_inputs[sid0 + s]);
        h0[s] = __ldg(&g_hbar[(sid0 + s) * ND + lane]);
        h1[s] = __ldg(&g_hbar[(sid0 + s) * ND + 32 + lane]);
    }

    float u0[2], u1[2];
    {
        float b0 = __ldg(&ue_b2[2 * lane]), b1 = __ldg(&ue_b2[2 * lane + 1]);
        #pragma unroll
        for (int s = 0; s < 2; s++) { u0[s] = b0; u1[s] = b1; }
    }
    #pragma unroll
    for (int k = 0; k < 64; k++) {
        float2 w = __ldg((const float2*)&ue_W2[k * 64 + 2 * lane]);
        #pragma unroll
        for (int s = 0; s < 2; s++) {
            float a = __shfl_sync(FULL, (k < 32) ? h0[s] : h1[s], k & 31);
            u0[s] += a * w.x; u1[s] += a * w.y;
        }
    }
    #pragma unroll
    for (int s = 0; s < 2; s++) { u0[s] = fmaxf(u0[s], 0.f); u1[s] = fmaxf(u1[s], 0.f); }

    float z0[2], z1[2], z2[2];
    {
        float b0 = __ldg(&ge_b1[lane]), b1 = __ldg(&ge_b1[lane + 32]), b2 = __ldg(&ge_b1[lane + 64]);
        #pragma unroll
        for (int s = 0; s < 2; s++) { z0[s] = b0; z1[s] = b1; z2[s] = b2; }
    }
    #pragma unroll
    for (int k = 0; k < 64; k++) {
        float w0 = __ldg(&ge_W1[k * 96 + lane]);
        float w1 = __ldg(&ge_W1[k * 96 + 32 + lane]);
        float w2 = __ldg(&ge_W1[k * 96 + 64 + lane]);
        #pragma unroll
        for (int s = 0; s < 2; s++) {
            float a = __shfl_sync(FULL, (k & 1) ? u1[s] : u0[s], k >> 1);
            z0[s] += a * w0; z1[s] += a * w1; z2[s] += a * w2;
        }
    }
    #pragma unroll
    for (int s = 0; s < 2; s++) {
        z0[s] = fmaxf(z0[s], 0.f); z1[s] = fmaxf(z1[s], 0.f); z2[s] = fmaxf(z2[s], 0.f);
    }

    float m0[2], m1[2];
    {
        float b0 = __ldg(&ge_b2[2 * lane]), b1 = __ldg(&ge_b2[2 * lane + 1]);
        #pragma unroll
        for (int s = 0; s < 2; s++) { m0[s] = b0; m1[s] = b1; }
    }
    #pragma unroll
    for (int k = 0; k < 96; k++) {
        float2 w = __ldg((const float2*)&ge_W2[k * 128 + 2 * lane]);
        #pragma unroll
        for (int s = 0; s < 2; s++) {
            float a = __shfl_sync(FULL, (k < 32) ? z0[s] : ((k < 64) ? z1[s] : z2[s]), k & 31);
            m0[s] += a * w.x; m1[s] += a * w.y;
        }
    }
    float gev0[2], gev1[2];
    #pragma unroll
    for (int s = 0; s < 2; s++) {
        float2 ge = __ldg((const float2*)&group_emb[gidx[s] * ND + 2 * lane]);
        gev0[s] = ge.x; gev1[s] = ge.y;
        float d0 = ge.x - m0[s], d1 = ge.y - m1[s];
        float p = d0 * d0 + d1 * d1;
        #pragma unroll
        for (int o = 16; o > 0; o >>= 1) p += __shfl_xor_sync(FULL, p, o);
        if (lane == 0) g_dkl_partial[sid0 + s] = p;
    }

    #pragma unroll
    for (int s = 0; s < 2; s++) {
        float2 itv = __ldg((const float2*)&item_emb[iidx[s] * ND + 2 * lane]);
        float2 gav = __ldg((const float2*)&g_gatt[(sid0 + s) * ND + 2 * lane]);
        float g0 = gav.x + gev0[s], g1 = gav.y + gev1[s];
        float hj[8] = {};
        #pragma unroll
        for (int cc = 0; cc < 2; cc++) {
            int col = 2 * lane + cc;
            float gg = cc ? g1 : g0;
            float iv = cc ? itv.y : itv.x;
            float v = gg * iv;
            float4 wa0 = ld4(&pr_W1[col * 8]),         wa1 = ld4(&pr_W1[col * 8 + 4]);
            float4 wb0 = ld4(&pr_W1[(64 + col) * 8]),  wb1 = ld4(&pr_W1[(64 + col) * 8 + 4]);
            float4 wc0 = ld4(&pr_W1[(128 + col) * 8]), wc1 = ld4(&pr_W1[(128 + col) * 8 + 4]);
            hj[0] += v * wa0.x + gg * wb0.x + iv * wc0.x;
            hj[1] += v * wa0.y + gg * wb0.y + iv * wc0.y;
            hj[2] += v * wa0.z + gg * wb0.z + iv * wc0.z;
            hj[3] += v * wa0.w + gg * wb0.w + iv * wc0.w;
            hj[4] += v * wa1.x + gg * wb1.x + iv * wc1.x;
            hj[5] += v * wa1.y + gg * wb1.y + iv * wc1.y;
            hj[6] += v * wa1.z + gg * wb1.z + iv * wc1.z;
            hj[7] += v * wa1.w + gg * wb1.w + iv * wc1.w;
        }
        #pragma unroll
        for (int j = 0; j < 8; j++) {
            #pragma unroll
            for (int o = 16; o > 0; o >>= 1) hj[j] += __shfl_xor_sync(FULL, hj[j], o);
        }
        if (lane == 0) {
            float acc = __ldg(&pr_b2[0]);
            #pragma unroll
            for (int j = 0; j < 8; j++)
                acc += fmaxf(hj[j] + __ldg(&pr_b1[j]), 0.f) * __ldg(&pr_W2[j]);
            y_out[sid0 + s] = 1.0f / (1.0f + __expf(-acc));
        }
    }

    __threadfence();
    __syncthreads();
    if (tid == 0) {
        unsigned t = atomicAdd(&g_count, 1u);
        s_last = (t == gridDim.x - 1);
    }
    __syncthreads();
    if (s_last) {
        float ss = 0.f;
        #pragma unroll
        for (int i = 0; i < NB / 256; i++) ss += g_dkl_partial[tid + i * 256];
        red[tid] = ss;
        __syncthreads();
        for (int st = 128; st > 0; st >>= 1) {
            if (tid < st) red[tid] += red[tid + st];
            __syncthreads();
        }
        if (tid == 0) {
            y_out[out_idx] = red[0] * (1.0f / (float)NB);
            g_count = 0;
            __threadfence();
        }
    }
}

extern "C" void kernel_launch(void* const* d_in, const int* in_sizes, int n_in,
                              void* d_out, int out_size)
{
    cudaFuncSetAttribute(agree_k1, cudaFuncAttributeMaxDynamicSharedMemorySize, SM1_BYTES);

    prep_kernel<<<(2560 + NB * 64 + 255) / 256, 256>>>(
        (const float*)d_in[6], (const float*)d_in[14],
        (const int*)d_in[0], (const int*)d_in[2]);

    agree_k1<<<NB / 2, 256, SM1_BYTES>>>(
        (const float*)d_in[3],   // user_emb
        (const int*)d_in[1],     // item_inputs
        (const float*)d_in[4],   // item_emb
        (const float*)d_in[7],   // ue_b1
        (const float*)d_in[14], (const float*)d_in[15],   // at_W1, at_b1
        (const float*)d_in[16], (const float*)d_in[17]);  // at_W2, at_b2

    agree_k2<<<NB / 16, 256>>>(
        (const int*)d_in[0],
        (const int*)d_in[1],
        (const float*)d_in[4],
        (const float*)d_in[5],
        (const float*)d_in[8],  (const float*)d_in[9],
        (const float*)d_in[10], (const float*)d_in[11],
        (const float*)d_in[12], (const float*)d_in[13],
        (const float*)d_in[18], (const float*)d_in[19],
        (const float*)d_in[20], (const float*)d_in[21],
        (float*)d_out, out_size - 1);
}